// round 2
// baseline (speedup 1.0000x reference)
#include <cuda_runtime.h>
#include <stdint.h>

#define NB   64
#define CIN  96
#define HWp  784
#define CMID 576
#define NPIX (NB*HWp)          // 50176
#define KW1  (CIN/4)           // 24
#define KW3  (CMID/4)          // 144
#define OUT_ELEMS (NB*CIN*HWp) // 4816896

// ---------------- device scratch ----------------
__device__ float    g_s[4];
__device__ uint32_t g_xq [NPIX*KW1];
__device__ uint32_t g_y1q[NPIX*KW3];
__device__ uint32_t g_y2q[NPIX*KW3];
__device__ uint32_t g_w1q[CMID*KW1];
__device__ uint32_t g_w2q[9*CMID/4];
__device__ uint32_t g_w3q[CIN*KW3];
__device__ float g_a1[CMID], g_bb1[CMID];
__device__ float g_a2[CMID], g_bb2[CMID];
__device__ float g_a3[CIN],  g_bb3[CIN];

__device__ __forceinline__ float clampf(float v, float lo, float hi){ return fminf(fmaxf(v,lo),hi); }
__device__ __forceinline__ int   sxb(uint32_t u, int k){ return ((int)(u << ((3-k)*8))) >> 24; }

// ---------------- prep ----------------
__global__ void k_params(const float* __restrict__ r0, const float* __restrict__ r1,
                         const float* __restrict__ r2, const float* __restrict__ r3,
                         const int* __restrict__ cl_){
    int cl = cl_[0];
    g_s[0]=r0[cl]/127.0f; g_s[1]=r1[cl]/127.0f; g_s[2]=r2[cl]/127.0f; g_s[3]=r3[cl]/127.0f;
}

// conv1 weights: (576,96) -> int8 codes, per-output-channel scale. block = one channel, 96 threads
__global__ void k_prep1(const float* __restrict__ w, const float* __restrict__ g,
                        const float* __restrict__ b, const float* __restrict__ m,
                        const float* __restrict__ v){
    int o = blockIdx.x, t = threadIdx.x;           // t < 96
    float sc = g[o] / sqrtf(v[o] + 1e-5f);
    float wf = w[o*CIN + t] * sc;
    float amx = fabsf(wf);
    __shared__ float red[3];
    #pragma unroll
    for (int off=16; off; off>>=1) amx = fmaxf(amx, __shfl_xor_sync(0xffffffffu, amx, off));
    if ((t & 31) == 0) red[t>>5] = amx;
    __syncthreads();
    float mx = fmaxf(red[0], fmaxf(red[1], red[2]));
    float sw = mx / 127.0f;
    float q  = clampf(rintf(wf / sw), -127.f, 127.f);
    ((int8_t*)g_w1q)[o*CIN + t] = (int8_t)q;
    if (t == 0){ g_a1[o] = g_s[0]*sw; g_bb1[o] = b[o] - m[o]*sc; }
}

// depthwise weights: (576,9). thread per channel, store transposed [tap][576]
__global__ void k_prep2(const float* __restrict__ w, const float* __restrict__ g,
                        const float* __restrict__ b, const float* __restrict__ m,
                        const float* __restrict__ v){
    int c = blockIdx.x*64 + threadIdx.x;           // 9*64 = 576 exact
    float sc = g[c] / sqrtf(v[c] + 1e-5f);
    float wf[9]; float mx = 0.f;
    #pragma unroll
    for (int j=0;j<9;j++){ wf[j] = w[c*9+j]*sc; mx = fmaxf(mx, fabsf(wf[j])); }
    float sw = mx / 127.0f;
    #pragma unroll
    for (int j=0;j<9;j++){
        float q = clampf(rintf(wf[j]/sw), -127.f, 127.f);
        ((int8_t*)g_w2q)[j*CMID + c] = (int8_t)q;
    }
    g_a2[c] = g_s[1]*sw; g_bb2[c] = b[c] - m[c]*sc;
}

// conv3 weights: (96,576). block = one channel, 192 threads x 3 elems
__global__ void k_prep3(const float* __restrict__ w, const float* __restrict__ g,
                        const float* __restrict__ b, const float* __restrict__ m,
                        const float* __restrict__ v){
    int o = blockIdx.x, t = threadIdx.x;           // t < 192
    float sc = g[o] / sqrtf(v[o] + 1e-5f);
    float f0 = w[o*CMID + t      ]*sc;
    float f1 = w[o*CMID + t + 192]*sc;
    float f2 = w[o*CMID + t + 384]*sc;
    float amx = fmaxf(fabsf(f0), fmaxf(fabsf(f1), fabsf(f2)));
    __shared__ float red[6];
    #pragma unroll
    for (int off=16; off; off>>=1) amx = fmaxf(amx, __shfl_xor_sync(0xffffffffu, amx, off));
    if ((t & 31) == 0) red[t>>5] = amx;
    __syncthreads();
    float mx = red[0];
    #pragma unroll
    for (int i=1;i<6;i++) mx = fmaxf(mx, red[i]);
    float sw = mx / 127.0f;
    int8_t* dst = (int8_t*)g_w3q + o*CMID;
    dst[t      ] = (int8_t)clampf(rintf(f0/sw), -127.f, 127.f);
    dst[t + 192] = (int8_t)clampf(rintf(f1/sw), -127.f, 127.f);
    dst[t + 384] = (int8_t)clampf(rintf(f2/sw), -127.f, 127.f);
    if (t == 0){ g_a3[o] = g_s[2]*sw; g_bb3[o] = b[o] - m[o]*sc; }
}

// ---------------- stage 0: quantize x (NCHW fp32 -> NHWC int8) ----------------
__global__ __launch_bounds__(128) void k_qx(const float* __restrict__ x){
    __shared__ int8_t sq[CIN*128];
    int t  = threadIdx.x;
    int p0 = blockIdx.x*128;
    int p  = p0 + t;
    int b  = p / HWp, hw = p % HWp;
    const float* xb = x + (size_t)b*CIN*HWp + hw;
    float s0 = g_s[0];
    #pragma unroll 4
    for (int c=0;c<CIN;c++){
        float q = clampf(rintf(xb[(size_t)c*HWp] / s0), -127.f, 127.f);
        sq[c*128 + t] = (int8_t)q;
    }
    __syncthreads();
    uint32_t* ow = g_xq + (size_t)p0*KW1;
    for (int w=t; w<128*KW1; w+=128){
        int pl = w / KW1;
        int c0 = (w % KW1)*4;
        uint32_t v =  (uint32_t)(uint8_t)sq[(c0+0)*128+pl]
                   | ((uint32_t)(uint8_t)sq[(c0+1)*128+pl] << 8)
                   | ((uint32_t)(uint8_t)sq[(c0+2)*128+pl] << 16)
                   | ((uint32_t)(uint8_t)sq[(c0+3)*128+pl] << 24);
        ow[w] = v;
    }
}

// ---------------- stage 1: 1x1 expand conv (int8 GEMM 50176x576x96) ----------------
#define ST2 68
__global__ __launch_bounds__(128) void k_conv1(){
    __shared__ __align__(16) uint32_t sA[KW1*ST2];
    __shared__ __align__(16) uint32_t sB[KW1*ST2];
    int t  = threadIdx.x;
    int p0 = blockIdx.x*64;
    int c0 = blockIdx.y*64;
    const uint32_t* A  = g_xq  + (size_t)p0*KW1;
    const uint32_t* Bw = g_w1q + (size_t)c0*KW1;
    for (int i=t; i<64*KW1; i+=128){
        int r = i/KW1, kw = i%KW1;
        sA[kw*ST2 + r] = A[i];
        sB[kw*ST2 + r] = Bw[i];
    }
    __syncthreads();
    int pg = t & 15, cg = t >> 4;
    int acc[4][8];
    #pragma unroll
    for (int i=0;i<4;i++){
        #pragma unroll
        for (int j=0;j<8;j++) acc[i][j] = 0;
    }
    #pragma unroll 4
    for (int kw=0; kw<KW1; kw++){
        uint4 av = *(const uint4*)&sA[kw*ST2 + pg*4];
        uint4 b0 = *(const uint4*)&sB[kw*ST2 + cg*8];
        uint4 b1 = *(const uint4*)&sB[kw*ST2 + cg*8 + 4];
        uint32_t aa[4] = {av.x,av.y,av.z,av.w};
        uint32_t bb[8] = {b0.x,b0.y,b0.z,b0.w,b1.x,b1.y,b1.z,b1.w};
        #pragma unroll
        for (int i=0;i<4;i++){
            #pragma unroll
            for (int j=0;j<8;j++)
                acc[i][j] = __dp4a((int)aa[i], (int)bb[j], acc[i][j]);
        }
    }
    // epilogue: bias + ReLU6 + requant to int8 for next stage
    float al[8], be[8];
    int cb = c0 + cg*8;
    #pragma unroll
    for (int j=0;j<8;j++){ al[j] = g_a1[cb+j]; be[j] = g_bb1[cb+j]; }
    float s1 = g_s[1];
    __syncthreads();
    uint32_t* q32 = sA;   // 1024 words staging (64 px x 64 ch bytes)
    #pragma unroll
    for (int i=0;i<4;i++){
        uint32_t lo=0, hi=0;
        #pragma unroll
        for (int j=0;j<8;j++){
            float y = fmaf(al[j], (float)acc[i][j], be[j]);
            y = clampf(y, 0.f, 6.f);
            float q = fminf(rintf(y / s1), 127.f);
            uint32_t qi = (uint32_t)(int)q;
            if (j < 4) lo |= qi << (8*j); else hi |= qi << (8*(j-4));
        }
        int pl = pg*4 + i;
        q32[pl*16 + cg*2    ] = lo;
        q32[pl*16 + cg*2 + 1] = hi;
    }
    __syncthreads();
    int wb0 = blockIdx.y*16;
    for (int w=t; w<1024; w+=128){
        int pl = w >> 4, wb = w & 15;
        g_y1q[(size_t)(p0+pl)*KW3 + wb0 + wb] = q32[w];
    }
}

// ---------------- stage 2: 3x3 depthwise conv on int8 NHWC ----------------
__global__ __launch_bounds__(576) void k_dw(){
    int t  = threadIdx.x;
    int pl = t / 144, c4 = t % 144;
    int p  = blockIdx.x*4 + pl;
    int b  = p / HWp, r = p % HWp;
    int h  = r / 28, wc = r % 28;
    uint32_t wr[9];
    #pragma unroll
    for (int j=0;j<9;j++) wr[j] = g_w2q[j*144 + c4];
    int a0=0,a1=0,a2=0,a3=0;
    int base = b*HWp;
    #pragma unroll
    for (int dh=-1; dh<=1; dh++){
        int nh = h + dh;
        if ((unsigned)nh >= 28u) continue;
        #pragma unroll
        for (int dw=-1; dw<=1; dw++){
            int nw = wc + dw;
            if ((unsigned)nw >= 28u) continue;
            uint32_t u  = g_y1q[(size_t)(base + nh*28 + nw)*KW3 + c4];
            uint32_t wv = wr[(dh+1)*3 + (dw+1)];
            a0 += sxb(u,0)*sxb(wv,0);
            a1 += sxb(u,1)*sxb(wv,1);
            a2 += sxb(u,2)*sxb(wv,2);
            a3 += sxb(u,3)*sxb(wv,3);
        }
    }
    int c = c4*4;
    float s2 = g_s[2];
    int accs[4] = {a0,a1,a2,a3};
    uint32_t out = 0;
    #pragma unroll
    for (int k=0;k<4;k++){
        float y = fmaf(g_a2[c+k], (float)accs[k], g_bb2[c+k]);
        y = clampf(y, 0.f, 6.f);
        float q = fminf(rintf(y / s2), 127.f);
        out |= ((uint32_t)(int)q) << (8*k);
    }
    g_y2q[(size_t)p*KW3 + c4] = out;
}

// ---------------- stage 3: 1x1 project conv + residual + final quant ----------------
#define ST4A 68
#define ST4B 100
#define SM4  ((KW3*ST4A + KW3*ST4B)*4)
__global__ __launch_bounds__(128) void k_conv3(const float* __restrict__ x, float* __restrict__ out){
    extern __shared__ __align__(16) uint32_t sm[];
    uint32_t* sA = sm;
    uint32_t* sB = sm + KW3*ST4A;
    int t  = threadIdx.x;
    int p0 = blockIdx.x*64;
    const uint32_t* A = g_y2q + (size_t)p0*KW3;
    for (int i=t; i<64*KW3; i+=128){
        int r = i/KW3, kw = i%KW3;
        sA[kw*ST4A + r] = A[i];
    }
    for (int i=t; i<CIN*KW3; i+=128){
        int r = i/KW3, kw = i%KW3;
        sB[kw*ST4B + r] = g_w3q[i];
    }
    __syncthreads();
    int pg = t & 15, cg = t >> 4;
    int acc[4][12];
    #pragma unroll
    for (int i=0;i<4;i++){
        #pragma unroll
        for (int j=0;j<12;j++) acc[i][j] = 0;
    }
    #pragma unroll 3
    for (int kw=0; kw<KW3; kw++){
        uint4 av = *(const uint4*)&sA[kw*ST4A + pg*4];
        const uint32_t* bp = &sB[kw*ST4B + cg*12];
        uint4 b0 = *(const uint4*)bp;
        uint4 b1 = *(const uint4*)(bp + 4);
        uint4 b2 = *(const uint4*)(bp + 8);
        uint32_t aa[4]  = {av.x,av.y,av.z,av.w};
        uint32_t bb[12] = {b0.x,b0.y,b0.z,b0.w,b1.x,b1.y,b1.z,b1.w,b2.x,b2.y,b2.z,b2.w};
        #pragma unroll
        for (int i=0;i<4;i++){
            #pragma unroll
            for (int j=0;j<12;j++)
                acc[i][j] = __dp4a((int)aa[i], (int)bb[j], acc[i][j]);
        }
    }
    __syncthreads();
    float* sO = (float*)sm;   // 96*65 floats = 24960 B, fits in sA region
    #pragma unroll
    for (int j=0;j<12;j++){
        int c = cg*12 + j;
        float al = g_a3[c], be = g_bb3[c];
        #pragma unroll
        for (int i=0;i<4;i++)
            sO[c*65 + pg*4 + i] = fmaf(al, (float)acc[i][j], be);
    }
    __syncthreads();
    float s3 = g_s[3];
    for (int idx=t; idx<96*64; idx+=128){
        int c = idx >> 6, pl = idx & 63;
        int p = p0 + pl;
        int b = p / HWp, hw = p % HWp;
        size_t g = (size_t)b*CIN*HWp + (size_t)c*HWp + hw;
        float y = sO[c*65 + pl] + x[g];
        float q = clampf(rintf(y / s3), -127.f, 127.f);
        out[g] = q * s3;
    }
}

// second tuple element (scalar s3) if the harness flattened both outputs
__global__ void k_tail(float* __restrict__ out, int out_size){
    for (int i = OUT_ELEMS + threadIdx.x; i < out_size; i += blockDim.x)
        out[i] = g_s[3];
}

// ---------------- launch ----------------
extern "C" void kernel_launch(void* const* d_in, const int* in_sizes, int n_in,
                              void* d_out, int out_size){
    const float* x  = (const float*)d_in[0];
    const float* w1 = (const float*)d_in[1];
    const float* g1 = (const float*)d_in[2];
    const float* b1 = (const float*)d_in[3];
    const float* m1 = (const float*)d_in[4];
    const float* v1 = (const float*)d_in[5];
    const float* w2 = (const float*)d_in[6];
    const float* g2 = (const float*)d_in[7];
    const float* b2 = (const float*)d_in[8];
    const float* m2 = (const float*)d_in[9];
    const float* v2 = (const float*)d_in[10];
    const float* w3 = (const float*)d_in[11];
    const float* g3 = (const float*)d_in[12];
    const float* b3 = (const float*)d_in[13];
    const float* m3 = (const float*)d_in[14];
    const float* v3 = (const float*)d_in[15];
    const float* r0 = (const float*)d_in[16];
    const float* r1 = (const float*)d_in[17];
    const float* r2 = (const float*)d_in[18];
    const float* r3 = (const float*)d_in[19];
    const int*   cl = (const int*)d_in[20];

    cudaFuncSetAttribute(k_conv3, cudaFuncAttributeMaxDynamicSharedMemorySize, SM4);

    k_params<<<1, 1>>>(r0, r1, r2, r3, cl);
    k_prep1<<<CMID, 96>>>(w1, g1, b1, m1, v1);
    k_prep2<<<9, 64>>>(w2, g2, b2, m2, v2);
    k_prep3<<<CIN, 192>>>(w3, g3, b3, m3, v3);
    k_qx<<<NPIX/128, 128>>>(x);
    k_conv1<<<dim3(NPIX/64, CMID/64), 128>>>();
    k_dw<<<NPIX/4, 576>>>();
    k_conv3<<<NPIX/64, 128, SM4>>>(x, (float*)d_out);
    k_tail<<<1, 128>>>((float*)d_out, out_size);
}

// round 5
// speedup vs baseline: 1.1048x; 1.1048x over previous
#include <cuda_runtime.h>
#include <stdint.h>

#define NB   64
#define CIN  96
#define HWp  784
#define CMID 576
#define NPIX (NB*HWp)          // 50176
#define KW1  (CIN/4)           // 24
#define KW3  (CMID/4)          // 144
#define OUT_ELEMS (NB*CIN*HWp) // 4816896

// ---------------- device scratch ----------------
__device__ float    g_s[4];
__device__ uint32_t g_xq [NPIX*KW1];
__device__ uint32_t g_y1q[NPIX*KW3];
__device__ uint32_t g_y2q[NPIX*KW3];
__device__ uint32_t g_w1q[CMID*KW1];
__device__ uint32_t g_w2q[9*CMID/4];
__device__ uint32_t g_w3q[CIN*KW3];
__device__ float g_a1[CMID], g_bb1[CMID];
__device__ float g_a2[CMID], g_bb2[CMID];
__device__ float g_a3[CIN],  g_bb3[CIN];

__device__ __forceinline__ float clampf(float v, float lo, float hi){ return fminf(fmaxf(v,lo),hi); }
__device__ __forceinline__ int   sxb(uint32_t u, int k){ return ((int)(u << ((3-k)*8))) >> 24; }

__device__ __forceinline__ void imma(int& d0,int& d1,int& d2,int& d3,
                                     uint32_t a0,uint32_t a1,uint32_t a2,uint32_t a3,
                                     uint32_t b0,uint32_t b1){
    asm volatile("mma.sync.aligned.m16n8k32.row.col.s32.s8.s8.s32 "
                 "{%0,%1,%2,%3},{%4,%5,%6,%7},{%8,%9},{%0,%1,%2,%3};"
                 : "+r"(d0),"+r"(d1),"+r"(d2),"+r"(d3)
                 : "r"(a0),"r"(a1),"r"(a2),"r"(a3),"r"(b0),"r"(b1));
}

// ---------------- prep ----------------
__global__ void k_params(const float* __restrict__ r0, const float* __restrict__ r1,
                         const float* __restrict__ r2, const float* __restrict__ r3,
                         const int* __restrict__ cl_){
    int cl = cl_[0];
    g_s[0]=r0[cl]/127.0f; g_s[1]=r1[cl]/127.0f; g_s[2]=r2[cl]/127.0f; g_s[3]=r3[cl]/127.0f;
}

__global__ void k_prep1(const float* __restrict__ w, const float* __restrict__ g,
                        const float* __restrict__ b, const float* __restrict__ m,
                        const float* __restrict__ v){
    int o = blockIdx.x, t = threadIdx.x;           // t < 96
    float sc = g[o] / sqrtf(v[o] + 1e-5f);
    float wf = w[o*CIN + t] * sc;
    float amx = fabsf(wf);
    __shared__ float red[3];
    #pragma unroll
    for (int off=16; off; off>>=1) amx = fmaxf(amx, __shfl_xor_sync(0xffffffffu, amx, off));
    if ((t & 31) == 0) red[t>>5] = amx;
    __syncthreads();
    float mx = fmaxf(red[0], fmaxf(red[1], red[2]));
    float sw = mx / 127.0f;
    float q  = clampf(rintf(wf / sw), -127.f, 127.f);
    ((int8_t*)g_w1q)[o*CIN + t] = (int8_t)q;
    if (t == 0){ g_a1[o] = g_s[0]*sw; g_bb1[o] = b[o] - m[o]*sc; }
}

__global__ void k_prep2(const float* __restrict__ w, const float* __restrict__ g,
                        const float* __restrict__ b, const float* __restrict__ m,
                        const float* __restrict__ v){
    int c = blockIdx.x*64 + threadIdx.x;           // 9*64 = 576 exact
    float sc = g[c] / sqrtf(v[c] + 1e-5f);
    float wf[9]; float mx = 0.f;
    #pragma unroll
    for (int j=0;j<9;j++){ wf[j] = w[c*9+j]*sc; mx = fmaxf(mx, fabsf(wf[j])); }
    float sw = mx / 127.0f;
    #pragma unroll
    for (int j=0;j<9;j++){
        float q = clampf(rintf(wf[j]/sw), -127.f, 127.f);
        ((int8_t*)g_w2q)[j*CMID + c] = (int8_t)q;
    }
    g_a2[c] = g_s[1]*sw; g_bb2[c] = b[c] - m[c]*sc;
}

__global__ void k_prep3(const float* __restrict__ w, const float* __restrict__ g,
                        const float* __restrict__ b, const float* __restrict__ m,
                        const float* __restrict__ v){
    int o = blockIdx.x, t = threadIdx.x;           // t < 192
    float sc = g[o] / sqrtf(v[o] + 1e-5f);
    float f0 = w[o*CMID + t      ]*sc;
    float f1 = w[o*CMID + t + 192]*sc;
    float f2 = w[o*CMID + t + 384]*sc;
    float amx = fmaxf(fabsf(f0), fmaxf(fabsf(f1), fabsf(f2)));
    __shared__ float red[6];
    #pragma unroll
    for (int off=16; off; off>>=1) amx = fmaxf(amx, __shfl_xor_sync(0xffffffffu, amx, off));
    if ((t & 31) == 0) red[t>>5] = amx;
    __syncthreads();
    float mx = red[0];
    #pragma unroll
    for (int i=1;i<6;i++) mx = fmaxf(mx, red[i]);
    float sw = mx / 127.0f;
    int8_t* dst = (int8_t*)g_w3q + o*CMID;
    dst[t      ] = (int8_t)clampf(rintf(f0/sw), -127.f, 127.f);
    dst[t + 192] = (int8_t)clampf(rintf(f1/sw), -127.f, 127.f);
    dst[t + 384] = (int8_t)clampf(rintf(f2/sw), -127.f, 127.f);
    if (t == 0){ g_a3[o] = g_s[2]*sw; g_bb3[o] = b[o] - m[o]*sc; }
}

// ---------------- stage 0: quantize x (NCHW fp32 -> NHWC int8) ----------------
__global__ __launch_bounds__(128) void k_qx(const float* __restrict__ x){
    __shared__ int8_t sq[CIN*128];
    int t  = threadIdx.x;
    int p0 = blockIdx.x*128;
    int p  = p0 + t;
    int b  = p / HWp, hw = p % HWp;
    const float* xb = x + (size_t)b*CIN*HWp + hw;
    float s0 = g_s[0];
    #pragma unroll 4
    for (int c=0;c<CIN;c++){
        float q = clampf(rintf(xb[(size_t)c*HWp] / s0), -127.f, 127.f);
        sq[c*128 + t] = (int8_t)q;
    }
    __syncthreads();
    uint32_t* ow = g_xq + (size_t)p0*KW1;
    for (int w=t; w<128*KW1; w+=128){
        int pl = w / KW1;
        int c0 = (w % KW1)*4;
        uint32_t v =  (uint32_t)(uint8_t)sq[(c0+0)*128+pl]
                   | ((uint32_t)(uint8_t)sq[(c0+1)*128+pl] << 8)
                   | ((uint32_t)(uint8_t)sq[(c0+2)*128+pl] << 16)
                   | ((uint32_t)(uint8_t)sq[(c0+3)*128+pl] << 24);
        ow[w] = v;
    }
}

// ---------------- stage 1: 1x1 expand conv, IMMA GEMM 50176x576x96 ----------------
#define SA1 28   // padded row stride (words); 28r+w mod 32 conflict-free
__global__ __launch_bounds__(128) void k_conv1(){
    __shared__ __align__(16) uint32_t sA[128*SA1];  // 14336 B
    __shared__ __align__(16) uint32_t sB[64*SA1];   //  7168 B
    int t  = threadIdx.x;
    int p0 = blockIdx.x*128;
    int c0 = blockIdx.y*64;
    const uint32_t* A  = g_xq  + (size_t)p0*KW1;
    const uint32_t* Bw = g_w1q + (size_t)c0*KW1;
    for (int i=t; i<128*6; i+=128){
        int r = i/6, q = i%6;
        *(uint4*)&sA[r*SA1 + q*4] = *(const uint4*)&A[r*KW1 + q*4];
    }
    for (int i=t; i<64*6; i+=128){
        int r = i/6, q = i%6;
        *(uint4*)&sB[r*SA1 + q*4] = *(const uint4*)&Bw[r*KW1 + q*4];
    }
    __syncthreads();
    int lane = t & 31, warp = t >> 5;
    int m0 = (warp & 1)*64, n0 = (warp >> 1)*32;
    int r4 = lane >> 2, w4 = lane & 3;
    int acc[4][4][4] = {};
    #pragma unroll
    for (int kc=0; kc<3; kc++){
        int ko = kc*8 + w4;
        uint32_t a[4][4], b[4][2];
        #pragma unroll
        for (int mi=0; mi<4; mi++){
            int rb = (m0 + mi*16 + r4)*SA1 + ko;
            a[mi][0] = sA[rb];            a[mi][1] = sA[rb + 8*SA1];
            a[mi][2] = sA[rb + 4];        a[mi][3] = sA[rb + 8*SA1 + 4];
        }
        #pragma unroll
        for (int ni=0; ni<4; ni++){
            int rb = (n0 + ni*8 + r4)*SA1 + ko;
            b[ni][0] = sB[rb];  b[ni][1] = sB[rb + 4];
        }
        #pragma unroll
        for (int mi=0; mi<4; mi++)
            #pragma unroll
            for (int ni=0; ni<4; ni++)
                imma(acc[mi][ni][0], acc[mi][ni][1], acc[mi][ni][2], acc[mi][ni][3],
                     a[mi][0], a[mi][1], a[mi][2], a[mi][3], b[ni][0], b[ni][1]);
    }
    // epilogue: bias + ReLU6 + requant -> int8, staged via smem
    float s1 = g_s[1];
    __syncthreads();
    uint16_t* sq = (uint16_t*)sA;   // [128 pix][32 u16] = 8 KB
    #pragma unroll
    for (int ni=0; ni<4; ni++){
        int cl = n0 + ni*8 + 2*w4;
        int cg = c0 + cl;
        float a0f = g_a1[cg],  a1f = g_a1[cg+1];
        float b0f = g_bb1[cg], b1f = g_bb1[cg+1];
        #pragma unroll
        for (int mi=0; mi<4; mi++){
            int row0 = m0 + mi*16 + r4;
            float y0 = clampf(fmaf(a0f, (float)acc[mi][ni][0], b0f), 0.f, 6.f);
            float y1 = clampf(fmaf(a1f, (float)acc[mi][ni][1], b1f), 0.f, 6.f);
            uint32_t q0 = (uint32_t)(int)fminf(rintf(y0/s1), 127.f);
            uint32_t q1 = (uint32_t)(int)fminf(rintf(y1/s1), 127.f);
            sq[row0*32 + (cl>>1)] = (uint16_t)((q0 & 0xff) | (q1 << 8));
            float y2 = clampf(fmaf(a0f, (float)acc[mi][ni][2], b0f), 0.f, 6.f);
            float y3 = clampf(fmaf(a1f, (float)acc[mi][ni][3], b1f), 0.f, 6.f);
            uint32_t q2 = (uint32_t)(int)fminf(rintf(y2/s1), 127.f);
            uint32_t q3 = (uint32_t)(int)fminf(rintf(y3/s1), 127.f);
            sq[(row0+8)*32 + (cl>>1)] = (uint16_t)((q2 & 0xff) | (q3 << 8));
        }
    }
    __syncthreads();
    const uint32_t* sq32 = (const uint32_t*)sq;
    int wb0 = blockIdx.y*16;
    for (int w=t; w<128*16; w+=128){
        int pl = w >> 4, wb = w & 15;
        g_y1q[(size_t)(p0+pl)*KW3 + wb0 + wb] = sq32[pl*16 + wb];
    }
}

// ---------------- stage 2: 3x3 depthwise conv on int8 NHWC ----------------
__global__ __launch_bounds__(576) void k_dw(){
    int t  = threadIdx.x;
    int pl = t / 144, c4 = t % 144;
    int p  = blockIdx.x*4 + pl;
    int b  = p / HWp, r = p % HWp;
    int h  = r / 28, wc = r % 28;
    uint32_t wr[9];
    #pragma unroll
    for (int j=0;j<9;j++) wr[j] = g_w2q[j*144 + c4];
    int a0=0,a1=0,a2=0,a3=0;
    int base = b*HWp;
    #pragma unroll
    for (int dh=-1; dh<=1; dh++){
        int nh = h + dh;
        if ((unsigned)nh >= 28u) continue;
        #pragma unroll
        for (int dw=-1; dw<=1; dw++){
            int nw = wc + dw;
            if ((unsigned)nw >= 28u) continue;
            uint32_t u  = g_y1q[(size_t)(base + nh*28 + nw)*KW3 + c4];
            uint32_t wv = wr[(dh+1)*3 + (dw+1)];
            a0 += sxb(u,0)*sxb(wv,0);
            a1 += sxb(u,1)*sxb(wv,1);
            a2 += sxb(u,2)*sxb(wv,2);
            a3 += sxb(u,3)*sxb(wv,3);
        }
    }
    int c = c4*4;
    float s2 = g_s[2];
    int accs[4] = {a0,a1,a2,a3};
    uint32_t out = 0;
    #pragma unroll
    for (int k=0;k<4;k++){
        float y = fmaf(g_a2[c+k], (float)accs[k], g_bb2[c+k]);
        y = clampf(y, 0.f, 6.f);
        float q = fminf(rintf(y / s2), 127.f);
        out |= ((uint32_t)(int)q) << (8*k);
    }
    g_y2q[(size_t)p*KW3 + c4] = out;
}

// ---------------- stage 3: 1x1 project conv + residual + final quant (IMMA) ----------------
#define SA3 52            // A slab row stride (48 data words + pad)
#define SB3 148           // B row stride (144 + pad)
#define SO3 101           // fp32 staging stride (coprime with 32)
#define SM3_WORDS (128*SA3 + 96*SB3)
#define SM3_BYTES (SM3_WORDS*4)
__global__ __launch_bounds__(256) void k_conv3(const float* __restrict__ x, float* __restrict__ out){
    extern __shared__ __align__(16) uint32_t sm3[];
    uint32_t* sA = sm3;               // 128 x 52
    uint32_t* sB = sm3 + 128*SA3;     // 96 x 148
    int t = threadIdx.x;
    int p0 = blockIdx.x*128;
    const uint32_t* A = g_y2q + (size_t)p0*KW3;
    // load all of B (96x144 words)
    for (int i=t; i<96*36; i+=256){
        int r = i/36, q = i%36;
        *(uint4*)&sB[r*SB3 + q*4] = *(const uint4*)&g_w3q[r*KW3 + q*4];
    }
    // load A slab 0
    for (int i=t; i<128*12; i+=256){
        int r = i/12, q = i%12;
        *(uint4*)&sA[r*SA3 + q*4] = *(const uint4*)&A[r*KW3 + q*4];
    }
    __syncthreads();
    int lane = t & 31, warp = t >> 5;
    int m0 = (warp & 3)*32, n0 = (warp >> 2)*48;
    int r4 = lane >> 2, w4 = lane & 3;
    int acc[2][6][4] = {};
    for (int s=0; s<3; s++){
        #pragma unroll
        for (int kc=0; kc<6; kc++){
            int ko = kc*8 + w4;
            uint32_t a[2][4], b[6][2];
            #pragma unroll
            for (int mi=0; mi<2; mi++){
                int rb = (m0 + mi*16 + r4)*SA3 + ko;
                a[mi][0] = sA[rb];       a[mi][1] = sA[rb + 8*SA3];
                a[mi][2] = sA[rb + 4];   a[mi][3] = sA[rb + 8*SA3 + 4];
            }
            int kb = s*48 + kc*8 + w4;
            #pragma unroll
            for (int ni=0; ni<6; ni++){
                int rb = (n0 + ni*8 + r4)*SB3 + kb;
                b[ni][0] = sB[rb];  b[ni][1] = sB[rb + 4];
            }
            #pragma unroll
            for (int mi=0; mi<2; mi++)
                #pragma unroll
                for (int ni=0; ni<6; ni++)
                    imma(acc[mi][ni][0], acc[mi][ni][1], acc[mi][ni][2], acc[mi][ni][3],
                         a[mi][0], a[mi][1], a[mi][2], a[mi][3], b[ni][0], b[ni][1]);
        }
        if (s < 2){
            __syncthreads();
            for (int i=t; i<128*12; i+=256){
                int r = i/12, q = i%12;
                *(uint4*)&sA[r*SA3 + q*4] = *(const uint4*)&A[r*KW3 + (s+1)*48 + q*4];
            }
            __syncthreads();
        }
    }
    // epilogue: bias -> fp32 staged in smem (over sB region), then residual + quant
    __syncthreads();
    float* sO = (float*)sB;   // 128 x 101 floats = 51.7 KB <= 56.8 KB
    #pragma unroll
    for (int ni=0; ni<6; ni++){
        int c = n0 + ni*8 + 2*w4;
        float af0 = g_a3[c],  af1 = g_a3[c+1];
        float bf0 = g_bb3[c], bf1 = g_bb3[c+1];
        #pragma unroll
        for (int mi=0; mi<2; mi++){
            int row0 = m0 + mi*16 + r4;
            sO[row0*SO3 + c    ] = fmaf(af0, (float)acc[mi][ni][0], bf0);
            sO[row0*SO3 + c + 1] = fmaf(af1, (float)acc[mi][ni][1], bf1);
            sO[(row0+8)*SO3 + c    ] = fmaf(af0, (float)acc[mi][ni][2], bf0);
            sO[(row0+8)*SO3 + c + 1] = fmaf(af1, (float)acc[mi][ni][3], bf1);
        }
    }
    __syncthreads();
    float s3 = g_s[3];
    for (int idx=t; idx<96*128; idx+=256){
        int c = idx >> 7, pl = idx & 127;
        int p = p0 + pl;
        int b = p / HWp, hw = p % HWp;
        size_t g = (size_t)b*CIN*HWp + (size_t)c*HWp + hw;
        float y = sO[pl*SO3 + c] + x[g];
        float q = clampf(rintf(y / s3), -127.f, 127.f);
        out[g] = q * s3;
    }
}

// second tuple element (scalar s3) if the harness flattened both outputs
__global__ void k_tail(float* __restrict__ out, int out_size){
    for (int i = OUT_ELEMS + threadIdx.x; i < out_size; i += blockDim.x)
        out[i] = g_s[3];
}

// ---------------- launch ----------------
extern "C" void kernel_launch(void* const* d_in, const int* in_sizes, int n_in,
                              void* d_out, int out_size){
    const float* x  = (const float*)d_in[0];
    const float* w1 = (const float*)d_in[1];
    const float* g1 = (const float*)d_in[2];
    const float* b1 = (const float*)d_in[3];
    const float* m1 = (const float*)d_in[4];
    const float* v1 = (const float*)d_in[5];
    const float* w2 = (const float*)d_in[6];
    const float* g2 = (const float*)d_in[7];
    const float* b2 = (const float*)d_in[8];
    const float* m2 = (const float*)d_in[9];
    const float* v2 = (const float*)d_in[10];
    const float* w3 = (const float*)d_in[11];
    const float* g3 = (const float*)d_in[12];
    const float* b3 = (const float*)d_in[13];
    const float* m3 = (const float*)d_in[14];
    const float* v3 = (const float*)d_in[15];
    const float* r0 = (const float*)d_in[16];
    const float* r1 = (const float*)d_in[17];
    const float* r2 = (const float*)d_in[18];
    const float* r3 = (const float*)d_in[19];
    const int*   cl = (const int*)d_in[20];

    static int smem_set = 0;
    if (!smem_set){
        cudaFuncSetAttribute(k_conv3, cudaFuncAttributeMaxDynamicSharedMemorySize, SM3_BYTES);
        smem_set = 1;
    }

    k_params<<<1, 1>>>(r0, r1, r2, r3, cl);
    k_prep1<<<CMID, 96>>>(w1, g1, b1, m1, v1);
    k_prep2<<<9, 64>>>(w2, g2, b2, m2, v2);
    k_prep3<<<CIN, 192>>>(w3, g3, b3, m3, v3);
    k_qx<<<NPIX/128, 128>>>(x);
    k_conv1<<<dim3(NPIX/128, CMID/64), 128>>>();
    k_dw<<<NPIX/4, 576>>>();
    k_conv3<<<NPIX/128, 256, SM3_BYTES>>>(x, (float*)d_out);
    k_tail<<<1, 128>>>((float*)d_out, out_size);
}

// round 6
// speedup vs baseline: 1.9148x; 1.7332x over previous
#include <cuda_runtime.h>
#include <stdint.h>

#define NB   64
#define CIN  96
#define HWp  784
#define CMID 576
#define NPIX (NB*HWp)          // 50176
#define KW1  24                // 96/4
#define KW3  144               // 576/4
#define OUT_ELEMS (NB*CIN*HWp) // 4816896

// ---------------- device scratch ----------------
__device__ float    g_s[4];
__device__ uint32_t g_xq [NPIX*KW1];
__device__ uint32_t g_y2q[NPIX*KW3];
__device__ uint32_t g_w1q[CMID*KW1];
__device__ uint32_t g_w2q[CMID*3];     // per channel: 3 row-words (k0,k1,k2,0)
__device__ uint32_t g_w3q[CIN*KW3];
__device__ float g_a1[CMID], g_bb1[CMID];
__device__ float g_a2[CMID], g_bb2[CMID];
__device__ float g_a3[CIN],  g_bb3[CIN];

__device__ __forceinline__ float clampf(float v, float lo, float hi){ return fminf(fmaxf(v,lo),hi); }

__device__ __forceinline__ void imma(int& d0,int& d1,int& d2,int& d3,
                                     uint32_t a0,uint32_t a1,uint32_t a2,uint32_t a3,
                                     uint32_t b0,uint32_t b1){
    asm volatile("mma.sync.aligned.m16n8k32.row.col.s32.s8.s8.s32 "
                 "{%0,%1,%2,%3},{%4,%5,%6,%7},{%8,%9},{%0,%1,%2,%3};"
                 : "+r"(d0),"+r"(d1),"+r"(d2),"+r"(d3)
                 : "r"(a0),"r"(a1),"r"(a2),"r"(a3),"r"(b0),"r"(b1));
}

// ---------------- single prep kernel: 681 blocks ----------------
// blocks [0,576):   conv1 weight row o=bid          (96 active threads)
// blocks [576,585): depthwise weights, 64 ch/block  (64 active threads)
// blocks [585,681): conv3 weight row o=bid-585      (192 threads)
__global__ __launch_bounds__(192) void k_prep(
    const float* __restrict__ w1, const float* __restrict__ g1, const float* __restrict__ b1,
    const float* __restrict__ m1, const float* __restrict__ v1,
    const float* __restrict__ w2, const float* __restrict__ g2, const float* __restrict__ b2,
    const float* __restrict__ m2, const float* __restrict__ v2,
    const float* __restrict__ w3, const float* __restrict__ g3, const float* __restrict__ b3,
    const float* __restrict__ m3, const float* __restrict__ v3,
    const float* __restrict__ r0, const float* __restrict__ r1,
    const float* __restrict__ r2, const float* __restrict__ r3,
    const int* __restrict__ cl_)
{
    __shared__ float red[6];
    int bid = blockIdx.x, t = threadIdx.x;
    int cl = cl_[0];
    if (bid == 0 && t == 0){
        g_s[0]=r0[cl]/127.0f; g_s[1]=r1[cl]/127.0f;
        g_s[2]=r2[cl]/127.0f; g_s[3]=r3[cl]/127.0f;
    }
    if (bid < CMID){
        int o = bid;
        float sc = g1[o] * rsqrtf(v1[o] + 1e-5f);
        float wf = 0.f;
        if (t < 96) wf = w1[o*CIN + t] * sc;
        float amx = fabsf(wf);
        #pragma unroll
        for (int off=16; off; off>>=1) amx = fmaxf(amx, __shfl_xor_sync(0xffffffffu, amx, off));
        if ((t & 31) == 0) red[t>>5] = amx;
        __syncthreads();
        float mx = red[0];
        #pragma unroll
        for (int i=1;i<6;i++) mx = fmaxf(mx, red[i]);
        float sw = mx / 127.0f;
        if (t < 96){
            float q = clampf(rintf(wf / sw), -127.f, 127.f);
            ((int8_t*)g_w1q)[o*CIN + t] = (int8_t)q;
        }
        if (t == 0){
            float s0 = r0[cl]/127.0f;
            g_a1[o] = s0*sw; g_bb1[o] = b1[o] - m1[o]*sc;
        }
    } else if (bid < CMID + 9){
        if (t < 64){
            int c = (bid - CMID)*64 + t;
            float sc = g2[c] * rsqrtf(v2[c] + 1e-5f);
            float wf[9]; float mx = 0.f;
            #pragma unroll
            for (int j=0;j<9;j++){ wf[j] = w2[c*9+j]*sc; mx = fmaxf(mx, fabsf(wf[j])); }
            float sw = mx / 127.0f;
            #pragma unroll
            for (int dh=0; dh<3; dh++){
                uint32_t pk = 0;
                #pragma unroll
                for (int dw=0; dw<3; dw++){
                    int q = (int)clampf(rintf(wf[dh*3+dw]/sw), -127.f, 127.f);
                    pk |= ((uint32_t)(uint8_t)(int8_t)q) << (8*dw);
                }
                g_w2q[c*3 + dh] = pk;   // byte3 = 0
            }
            float s1 = r1[cl]/127.0f;
            g_a2[c] = s1*sw; g_bb2[c] = b2[c] - m2[c]*sc;
        }
    } else {
        int o = bid - (CMID + 9);
        float sc = g3[o] * rsqrtf(v3[o] + 1e-5f);
        float f0 = w3[o*CMID + t      ]*sc;
        float f1 = w3[o*CMID + t + 192]*sc;
        float f2 = w3[o*CMID + t + 384]*sc;
        float amx = fmaxf(fabsf(f0), fmaxf(fabsf(f1), fabsf(f2)));
        #pragma unroll
        for (int off=16; off; off>>=1) amx = fmaxf(amx, __shfl_xor_sync(0xffffffffu, amx, off));
        if ((t & 31) == 0) red[t>>5] = amx;
        __syncthreads();
        float mx = red[0];
        #pragma unroll
        for (int i=1;i<6;i++) mx = fmaxf(mx, red[i]);
        float sw = mx / 127.0f;
        int8_t* dst = (int8_t*)g_w3q + o*CMID;
        dst[t      ] = (int8_t)clampf(rintf(f0/sw), -127.f, 127.f);
        dst[t + 192] = (int8_t)clampf(rintf(f1/sw), -127.f, 127.f);
        dst[t + 384] = (int8_t)clampf(rintf(f2/sw), -127.f, 127.f);
        if (t == 0){
            float s2 = r2[cl]/127.0f;
            g_a3[o] = s2*sw; g_bb3[o] = b3[o] - m3[o]*sc;
        }
    }
}

// ---------------- stage 0: quantize x (NCHW fp32 -> NHWC int8 words) ----------------
__global__ __launch_bounds__(128) void k_qx(const float* __restrict__ x){
    __shared__ int8_t sq[CIN*128];
    int t  = threadIdx.x;
    int p0 = blockIdx.x*128;
    int p  = p0 + t;
    int b  = p / HWp, hw = p % HWp;
    const float* xb = x + (size_t)b*CIN*HWp + hw;
    float inv0 = 1.0f / g_s[0];
    #pragma unroll 4
    for (int c=0;c<CIN;c++){
        float q = clampf(rintf(xb[(size_t)c*HWp] * inv0), -127.f, 127.f);
        sq[c*128 + t] = (int8_t)q;
    }
    __syncthreads();
    uint32_t* ow = g_xq + (size_t)p0*KW1;
    for (int w=t; w<128*KW1; w+=128){
        int pl = w / KW1;
        int c0 = (w % KW1)*4;
        uint32_t v =  (uint32_t)(uint8_t)sq[(c0+0)*128+pl]
                   | ((uint32_t)(uint8_t)sq[(c0+1)*128+pl] << 8)
                   | ((uint32_t)(uint8_t)sq[(c0+2)*128+pl] << 16)
                   | ((uint32_t)(uint8_t)sq[(c0+3)*128+pl] << 24);
        ow[w] = v;
    }
}

// ---------------- fused conv1 (IMMA) + depthwise (dp4a rows) ----------------
// block = (chunk of 64 mid-channels, image). 256 threads.
#define SA 28            // xq / w1 smem row stride (words) — conflict-free frags
#define Y1W 197          // y1 channel-major stride in words (788 B, gcd(197,32)=1)
#define OFF_SW (HWp*SA)                    // 21952
#define OFF_Y1 (OFF_SW + 64*SA)            // +1792
#define OFF_Y2 (OFF_Y1 + 64*Y1W)           // +12608
#define SM1_WORDS (OFF_Y2 + HWp*16)        // +12544 = 48896
#define SM1_BYTES (SM1_WORDS*4)            // 195584
__global__ __launch_bounds__(256) void k_c1dw(){
    extern __shared__ __align__(16) uint32_t sm[];
    uint32_t* sA = sm;
    uint32_t* sW = sm + OFF_SW;
    uint32_t* y1 = sm + OFF_Y1;
    uint32_t* y2 = sm + OFF_Y2;
    int t   = threadIdx.x;
    int ch  = blockIdx.x;     // 0..8
    int img = blockIdx.y;     // 0..63

    const uint32_t* A = g_xq + (size_t)img*HWp*KW1;
    for (int i=t; i<HWp*6; i+=256){
        int r = i/6, q = i%6;
        *(uint4*)&sA[r*SA + q*4] = *(const uint4*)&A[r*KW1 + q*4];
    }
    const uint32_t* W = g_w1q + (size_t)ch*64*KW1;
    for (int i=t; i<64*6; i+=256){
        int r = i/6, q = i%6;
        *(uint4*)&sW[r*SA + q*4] = *(const uint4*)&W[r*KW1 + q*4];
    }
    __syncthreads();

    int lane = t & 31, warp = t >> 5, r4 = lane >> 2, w4 = lane & 3;
    // B fragments resident in registers (full 64-ch chunk, K=96)
    uint32_t bf[3][8][2];
    #pragma unroll
    for (int kc=0;kc<3;kc++)
        #pragma unroll
        for (int ni=0;ni<8;ni++){
            int rb = (ni*8 + r4)*SA + kc*8 + w4;
            bf[kc][ni][0] = sW[rb]; bf[kc][ni][1] = sW[rb+4];
        }
    float af[8][2], bb[8][2];
    #pragma unroll
    for (int ni=0;ni<8;ni++){
        int cg = ch*64 + ni*8 + 2*w4;
        af[ni][0] = g_a1[cg];  af[ni][1] = g_a1[cg+1];
        bb[ni][0] = g_bb1[cg]; bb[ni][1] = g_bb1[cg+1];
    }
    float inv1 = 1.0f / g_s[1];
    int8_t* y1b = (int8_t*)y1;

    for (int tile = warp; tile < 49; tile += 8){
        int m0 = tile*16;
        int acc[8][4] = {};
        #pragma unroll
        for (int kc=0;kc<3;kc++){
            int rb = (m0 + r4)*SA + kc*8 + w4;
            uint32_t a0 = sA[rb], a1 = sA[rb + 8*SA], a2 = sA[rb + 4], a3 = sA[rb + 8*SA + 4];
            #pragma unroll
            for (int ni=0;ni<8;ni++)
                imma(acc[ni][0],acc[ni][1],acc[ni][2],acc[ni][3],
                     a0,a1,a2,a3, bf[kc][ni][0], bf[kc][ni][1]);
        }
        int px0 = m0 + r4, px1 = px0 + 8;
        #pragma unroll
        for (int ni=0;ni<8;ni++){
            int c0 = ni*8 + 2*w4;
            float v0 = clampf(fmaf(af[ni][0], (float)acc[ni][0], bb[ni][0]), 0.f, 6.f);
            float v1 = clampf(fmaf(af[ni][1], (float)acc[ni][1], bb[ni][1]), 0.f, 6.f);
            float v2 = clampf(fmaf(af[ni][0], (float)acc[ni][2], bb[ni][0]), 0.f, 6.f);
            float v3 = clampf(fmaf(af[ni][1], (float)acc[ni][3], bb[ni][1]), 0.f, 6.f);
            y1b[ c0   *788 + px0] = (int8_t)(int)fminf(rintf(v0*inv1), 127.f);
            y1b[(c0+1)*788 + px0] = (int8_t)(int)fminf(rintf(v1*inv1), 127.f);
            y1b[ c0   *788 + px1] = (int8_t)(int)fminf(rintf(v2*inv1), 127.f);
            y1b[(c0+1)*788 + px1] = (int8_t)(int)fminf(rintf(v3*inv1), 127.f);
        }
    }
    __syncthreads();

    // depthwise 3x3 as 1D 3-tap dp4a rows; task = (channel-in-chunk, output row)
    float inv2 = 1.0f / g_s[2];
    int8_t* y2b = (int8_t*)y2;
    for (int task=t; task<64*28; task+=256){
        int c = task & 63, h = task >> 6;
        int cg = ch*64 + c;
        uint32_t wk0 = g_w2q[cg*3+0], wk1 = g_w2q[cg*3+1], wk2 = g_w2q[cg*3+2];
        float a2 = g_a2[cg], b2 = g_bb2[cg];
        const uint32_t* rw = y1 + c*Y1W;
        uint32_t rm[7], rc[7], rp[7];
        #pragma unroll
        for (int j=0;j<7;j++){
            rc[j] = rw[h*7 + j];
            rm[j] = (h > 0)  ? rw[(h-1)*7 + j] : 0u;
            rp[j] = (h < 27) ? rw[(h+1)*7 + j] : 0u;
        }
        uint32_t pm=0, pc=0, pp=0;
        #pragma unroll
        for (int j=0;j<7;j++){
            uint32_t nm = (j<6)? rm[j+1] : 0u;
            uint32_t nc = (j<6)? rc[j+1] : 0u;
            uint32_t np = (j<6)? rp[j+1] : 0u;
            int o0 = __dp4a((int)__byte_perm(pm, rm[j], 0x6543), (int)wk0, 0)
                   + __dp4a((int)__byte_perm(pc, rc[j], 0x6543), (int)wk1, 0)
                   + __dp4a((int)__byte_perm(pp, rp[j], 0x6543), (int)wk2, 0);
            int o1 = __dp4a((int)rm[j], (int)wk0, 0)
                   + __dp4a((int)rc[j], (int)wk1, 0)
                   + __dp4a((int)rp[j], (int)wk2, 0);
            int o2 = __dp4a((int)__byte_perm(rm[j], nm, 0x4321), (int)wk0, 0)
                   + __dp4a((int)__byte_perm(rc[j], nc, 0x4321), (int)wk1, 0)
                   + __dp4a((int)__byte_perm(rp[j], np, 0x4321), (int)wk2, 0);
            int o3 = __dp4a((int)__byte_perm(rm[j], nm, 0x5432), (int)wk0, 0)
                   + __dp4a((int)__byte_perm(rc[j], nc, 0x5432), (int)wk1, 0)
                   + __dp4a((int)__byte_perm(rp[j], np, 0x5432), (int)wk2, 0);
            int outs[4] = {o0, o1, o2, o3};
            #pragma unroll
            for (int i2=0;i2<4;i2++){
                float y = clampf(fmaf(a2, (float)outs[i2], b2), 0.f, 6.f);
                int q = (int)fminf(rintf(y*inv2), 127.f);
                y2b[(h*28 + j*4 + i2)*64 + c] = (int8_t)q;
            }
            pm = rm[j]; pc = rc[j]; pp = rp[j];
        }
    }
    __syncthreads();

    uint32_t* dst = g_y2q + (size_t)img*HWp*KW3 + ch*16;
    for (int i=t; i<HWp*4; i+=256){
        int p = i>>2, q = i&3;
        *(uint4*)&dst[(size_t)p*KW3 + q*4] = ((const uint4*)y2)[i];
    }
}

// ---------------- conv3: 1x1 project + residual + final quant ----------------
// tile 64 px x 96 ch, 128 threads (4 warps, each 16px x 96ch), 2 CTA/SM
#define SB3 148
#define SO3 101
#define SM3_WORDS (CIN*SB3 + 64*SB3)   // 14208 + 9472 = 23680
#define SM3_BYTES (SM3_WORDS*4)        // 94720
__global__ __launch_bounds__(128) void k_conv3(const float* __restrict__ x,
                                               float* __restrict__ out, int out_size){
    extern __shared__ __align__(16) uint32_t sm[];
    uint32_t* sB = sm;               // 96 x 148
    uint32_t* sA = sm + CIN*SB3;     // 64 x 148
    int t = threadIdx.x;
    int p0 = blockIdx.x*64;
    for (int i=t; i<CIN*36; i+=128){
        int r = i/36, q = i%36;
        *(uint4*)&sB[r*SB3 + q*4] = *(const uint4*)&g_w3q[r*KW3 + q*4];
    }
    const uint32_t* A = g_y2q + (size_t)p0*KW3;
    for (int i=t; i<64*36; i+=128){
        int r = i/36, q = i%36;
        *(uint4*)&sA[r*SB3 + q*4] = *(const uint4*)&A[r*KW3 + q*4];
    }
    __syncthreads();
    int lane = t & 31, warp = t >> 5, r4 = lane >> 2, w4 = lane & 3;
    int m0 = warp*16;
    int acc[12][4] = {};
    #pragma unroll 2
    for (int ks=0; ks<18; ks++){
        int rb = (m0 + r4)*SB3 + ks*8 + w4;
        uint32_t a0 = sA[rb], a1 = sA[rb + 8*SB3], a2 = sA[rb + 4], a3 = sA[rb + 8*SB3 + 4];
        #pragma unroll
        for (int ni=0; ni<12; ni++){
            int nb = (ni*8 + r4)*SB3 + ks*8 + w4;
            uint32_t b0 = sB[nb], b1 = sB[nb + 4];
            imma(acc[ni][0],acc[ni][1],acc[ni][2],acc[ni][3], a0,a1,a2,a3, b0,b1);
        }
    }
    __syncthreads();
    float* sO = (float*)sA;   // 64 x 101 floats = 25856 B, fits
    #pragma unroll
    for (int ni=0; ni<12; ni++){
        int c = ni*8 + 2*w4;
        float af0 = g_a3[c],  af1 = g_a3[c+1];
        float bf0 = g_bb3[c], bf1 = g_bb3[c+1];
        int row0 = m0 + r4;
        sO[ row0   *SO3 + c    ] = fmaf(af0, (float)acc[ni][0], bf0);
        sO[ row0   *SO3 + c + 1] = fmaf(af1, (float)acc[ni][1], bf1);
        sO[(row0+8)*SO3 + c    ] = fmaf(af0, (float)acc[ni][2], bf0);
        sO[(row0+8)*SO3 + c + 1] = fmaf(af1, (float)acc[ni][3], bf1);
    }
    __syncthreads();
    float s3 = g_s[3];
    float inv3 = 1.0f / s3;
    for (int idx=t; idx<CIN*64; idx+=128){
        int c = idx >> 6, pl = idx & 63;
        int p = p0 + pl;
        int b = p / HWp, hw = p % HWp;
        size_t g = (size_t)b*CIN*HWp + (size_t)c*HWp + hw;
        float y = sO[pl*SO3 + c] + x[g];
        float q = clampf(rintf(y*inv3), -127.f, 127.f);
        out[g] = q * s3;
    }
    if (blockIdx.x == 0){
        for (int i = OUT_ELEMS + t; i < out_size; i += 128) out[i] = g_s[3];
    }
}

// ---------------- launch ----------------
extern "C" void kernel_launch(void* const* d_in, const int* in_sizes, int n_in,
                              void* d_out, int out_size){
    const float* x  = (const float*)d_in[0];
    const float* w1 = (const float*)d_in[1];
    const float* g1 = (const float*)d_in[2];
    const float* b1 = (const float*)d_in[3];
    const float* m1 = (const float*)d_in[4];
    const float* v1 = (const float*)d_in[5];
    const float* w2 = (const float*)d_in[6];
    const float* g2 = (const float*)d_in[7];
    const float* b2 = (const float*)d_in[8];
    const float* m2 = (const float*)d_in[9];
    const float* v2 = (const float*)d_in[10];
    const float* w3 = (const float*)d_in[11];
    const float* g3 = (const float*)d_in[12];
    const float* b3 = (const float*)d_in[13];
    const float* m3 = (const float*)d_in[14];
    const float* v3 = (const float*)d_in[15];
    const float* r0 = (const float*)d_in[16];
    const float* r1 = (const float*)d_in[17];
    const float* r2 = (const float*)d_in[18];
    const float* r3 = (const float*)d_in[19];
    const int*   cl = (const int*)d_in[20];

    cudaFuncSetAttribute(k_c1dw,  cudaFuncAttributeMaxDynamicSharedMemorySize, SM1_BYTES);
    cudaFuncSetAttribute(k_conv3, cudaFuncAttributeMaxDynamicSharedMemorySize, SM3_BYTES);

    k_prep<<<CMID + 9 + CIN, 192>>>(w1,g1,b1,m1,v1, w2,g2,b2,m2,v2, w3,g3,b3,m3,v3,
                                    r0,r1,r2,r3, cl);
    k_qx<<<NPIX/128, 128>>>(x);
    k_c1dw<<<dim3(9, NB), 256, SM1_BYTES>>>();
    k_conv3<<<NPIX/64, 128, SM3_BYTES>>>(x, (float*)d_out, out_size);
}

// round 7
// speedup vs baseline: 1.9210x; 1.0032x over previous
#include <cuda_runtime.h>
#include <stdint.h>

#define NB   64
#define CIN  96
#define HWp  784
#define CMID 576
#define NPIX (NB*HWp)          // 50176
#define KW1  24                // 96/4
#define KW3  144               // 576/4
#define OUT_ELEMS (NB*CIN*HWp) // 4816896

// ---------------- device scratch ----------------
__device__ float    g_s[4];
__device__ uint32_t g_xq [NPIX*KW1];
__device__ uint32_t g_y2q[NPIX*KW3];
__device__ uint32_t g_w1q[CMID*KW1];
__device__ uint32_t g_w2q[CMID*3];     // per channel: 3 row-words (k0,k1,k2,0)
__device__ uint32_t g_w3q[CIN*KW3];
__device__ float g_a1[CMID], g_bb1[CMID];
__device__ float g_a2[CMID], g_bb2[CMID];
__device__ float g_a3[CIN],  g_bb3[CIN];

__device__ __forceinline__ float clampf(float v, float lo, float hi){ return fminf(fmaxf(v,lo),hi); }

__device__ __forceinline__ void imma(int& d0,int& d1,int& d2,int& d3,
                                     uint32_t a0,uint32_t a1,uint32_t a2,uint32_t a3,
                                     uint32_t b0,uint32_t b1){
    asm volatile("mma.sync.aligned.m16n8k32.row.col.s32.s8.s8.s32 "
                 "{%0,%1,%2,%3},{%4,%5,%6,%7},{%8,%9},{%0,%1,%2,%3};"
                 : "+r"(d0),"+r"(d1),"+r"(d2),"+r"(d3)
                 : "r"(a0),"r"(a1),"r"(a2),"r"(a3),"r"(b0),"r"(b1));
}

// ---------------- single prep kernel: 681 blocks ----------------
__global__ __launch_bounds__(192) void k_prep(
    const float* __restrict__ w1, const float* __restrict__ g1, const float* __restrict__ b1,
    const float* __restrict__ m1, const float* __restrict__ v1,
    const float* __restrict__ w2, const float* __restrict__ g2, const float* __restrict__ b2,
    const float* __restrict__ m2, const float* __restrict__ v2,
    const float* __restrict__ w3, const float* __restrict__ g3, const float* __restrict__ b3,
    const float* __restrict__ m3, const float* __restrict__ v3,
    const float* __restrict__ r0, const float* __restrict__ r1,
    const float* __restrict__ r2, const float* __restrict__ r3,
    const int* __restrict__ cl_)
{
    __shared__ float red[6];
    int bid = blockIdx.x, t = threadIdx.x;
    int cl = cl_[0];
    if (bid == 0 && t == 0){
        g_s[0]=r0[cl]/127.0f; g_s[1]=r1[cl]/127.0f;
        g_s[2]=r2[cl]/127.0f; g_s[3]=r3[cl]/127.0f;
    }
    if (bid < CMID){
        int o = bid;
        float sc = g1[o] * rsqrtf(v1[o] + 1e-5f);
        float wf = 0.f;
        if (t < 96) wf = w1[o*CIN + t] * sc;
        float amx = fabsf(wf);
        #pragma unroll
        for (int off=16; off; off>>=1) amx = fmaxf(amx, __shfl_xor_sync(0xffffffffu, amx, off));
        if ((t & 31) == 0) red[t>>5] = amx;
        __syncthreads();
        float mx = red[0];
        #pragma unroll
        for (int i=1;i<6;i++) mx = fmaxf(mx, red[i]);
        float sw = mx / 127.0f;
        if (t < 96){
            float q = clampf(rintf(wf / sw), -127.f, 127.f);
            ((int8_t*)g_w1q)[o*CIN + t] = (int8_t)q;
        }
        if (t == 0){
            float s0 = r0[cl]/127.0f;
            g_a1[o] = s0*sw; g_bb1[o] = b1[o] - m1[o]*sc;
        }
    } else if (bid < CMID + 9){
        if (t < 64){
            int c = (bid - CMID)*64 + t;
            float sc = g2[c] * rsqrtf(v2[c] + 1e-5f);
            float wf[9]; float mx = 0.f;
            #pragma unroll
            for (int j=0;j<9;j++){ wf[j] = w2[c*9+j]*sc; mx = fmaxf(mx, fabsf(wf[j])); }
            float sw = mx / 127.0f;
            #pragma unroll
            for (int dh=0; dh<3; dh++){
                uint32_t pk = 0;
                #pragma unroll
                for (int dw=0; dw<3; dw++){
                    int q = (int)clampf(rintf(wf[dh*3+dw]/sw), -127.f, 127.f);
                    pk |= ((uint32_t)(uint8_t)(int8_t)q) << (8*dw);
                }
                g_w2q[c*3 + dh] = pk;   // byte3 = 0
            }
            float s1 = r1[cl]/127.0f;
            g_a2[c] = s1*sw; g_bb2[c] = b2[c] - m2[c]*sc;
        }
    } else {
        int o = bid - (CMID + 9);
        float sc = g3[o] * rsqrtf(v3[o] + 1e-5f);
        float f0 = w3[o*CMID + t      ]*sc;
        float f1 = w3[o*CMID + t + 192]*sc;
        float f2 = w3[o*CMID + t + 384]*sc;
        float amx = fmaxf(fabsf(f0), fmaxf(fabsf(f1), fabsf(f2)));
        #pragma unroll
        for (int off=16; off; off>>=1) amx = fmaxf(amx, __shfl_xor_sync(0xffffffffu, amx, off));
        if ((t & 31) == 0) red[t>>5] = amx;
        __syncthreads();
        float mx = red[0];
        #pragma unroll
        for (int i=1;i<6;i++) mx = fmaxf(mx, red[i]);
        float sw = mx / 127.0f;
        int8_t* dst = (int8_t*)g_w3q + o*CMID;
        dst[t      ] = (int8_t)clampf(rintf(f0/sw), -127.f, 127.f);
        dst[t + 192] = (int8_t)clampf(rintf(f1/sw), -127.f, 127.f);
        dst[t + 384] = (int8_t)clampf(rintf(f2/sw), -127.f, 127.f);
        if (t == 0){
            float s2 = r2[cl]/127.0f;
            g_a3[o] = s2*sw; g_bb3[o] = b3[o] - m3[o]*sc;
        }
    }
}

// ---------------- stage 0: quantize x (NCHW fp32 -> NHWC int8 words) ----------------
__global__ __launch_bounds__(128) void k_qx(const float* __restrict__ x){
    __shared__ int8_t sq[CIN*128];
    int t  = threadIdx.x;
    int p0 = blockIdx.x*128;
    int p  = p0 + t;
    int b  = p / HWp, hw = p % HWp;
    const float* xb = x + (size_t)b*CIN*HWp + hw;
    float inv0 = 1.0f / g_s[0];
    #pragma unroll 4
    for (int c=0;c<CIN;c++){
        float q = clampf(rintf(xb[(size_t)c*HWp] * inv0), -127.f, 127.f);
        sq[c*128 + t] = (int8_t)q;
    }
    __syncthreads();
    uint32_t* ow = g_xq + (size_t)p0*KW1;
    for (int w=t; w<128*KW1; w+=128){
        int pl = w / KW1;
        int c0 = (w % KW1)*4;
        uint32_t v =  (uint32_t)(uint8_t)sq[(c0+0)*128+pl]
                   | ((uint32_t)(uint8_t)sq[(c0+1)*128+pl] << 8)
                   | ((uint32_t)(uint8_t)sq[(c0+2)*128+pl] << 16)
                   | ((uint32_t)(uint8_t)sq[(c0+3)*128+pl] << 24);
        ow[w] = v;
    }
}

// ---------------- fused conv1 (IMMA) + depthwise (dp4a rows) ----------------
#define SA 28
#define Y1W 197
#define OFF_SW (HWp*SA)
#define OFF_Y1 (OFF_SW + 64*SA)
#define OFF_Y2 (OFF_Y1 + 64*Y1W)
#define SM1_WORDS (OFF_Y2 + HWp*16)
#define SM1_BYTES (SM1_WORDS*4)            // 195584
__global__ __launch_bounds__(256) void k_c1dw(){
    extern __shared__ __align__(16) uint32_t sm[];
    uint32_t* sA = sm;
    uint32_t* sW = sm + OFF_SW;
    uint32_t* y1 = sm + OFF_Y1;
    uint32_t* y2 = sm + OFF_Y2;
    int t   = threadIdx.x;
    int ch  = blockIdx.x;     // 0..8
    int img = blockIdx.y;     // 0..63

    const uint32_t* A = g_xq + (size_t)img*HWp*KW1;
    for (int i=t; i<HWp*6; i+=256){
        int r = i/6, q = i%6;
        *(uint4*)&sA[r*SA + q*4] = *(const uint4*)&A[r*KW1 + q*4];
    }
    const uint32_t* W = g_w1q + (size_t)ch*64*KW1;
    for (int i=t; i<64*6; i+=256){
        int r = i/6, q = i%6;
        *(uint4*)&sW[r*SA + q*4] = *(const uint4*)&W[r*KW1 + q*4];
    }
    __syncthreads();

    int lane = t & 31, warp = t >> 5, r4 = lane >> 2, w4 = lane & 3;
    uint32_t bf[3][8][2];
    #pragma unroll
    for (int kc=0;kc<3;kc++)
        #pragma unroll
        for (int ni=0;ni<8;ni++){
            int rb = (ni*8 + r4)*SA + kc*8 + w4;
            bf[kc][ni][0] = sW[rb]; bf[kc][ni][1] = sW[rb+4];
        }
    float af[8][2], bb[8][2];
    #pragma unroll
    for (int ni=0;ni<8;ni++){
        int cg = ch*64 + ni*8 + 2*w4;
        af[ni][0] = g_a1[cg];  af[ni][1] = g_a1[cg+1];
        bb[ni][0] = g_bb1[cg]; bb[ni][1] = g_bb1[cg+1];
    }
    float inv1 = 1.0f / g_s[1];
    int8_t* y1b = (int8_t*)y1;

    for (int tile = warp; tile < 49; tile += 8){
        int m0 = tile*16;
        int acc[8][4] = {};
        #pragma unroll
        for (int kc=0;kc<3;kc++){
            int rb = (m0 + r4)*SA + kc*8 + w4;
            uint32_t a0 = sA[rb], a1 = sA[rb + 8*SA], a2 = sA[rb + 4], a3 = sA[rb + 8*SA + 4];
            #pragma unroll
            for (int ni=0;ni<8;ni++)
                imma(acc[ni][0],acc[ni][1],acc[ni][2],acc[ni][3],
                     a0,a1,a2,a3, bf[kc][ni][0], bf[kc][ni][1]);
        }
        int px0 = m0 + r4, px1 = px0 + 8;
        #pragma unroll
        for (int ni=0;ni<8;ni++){
            int c0 = ni*8 + 2*w4;
            float v0 = clampf(fmaf(af[ni][0], (float)acc[ni][0], bb[ni][0]), 0.f, 6.f);
            float v1 = clampf(fmaf(af[ni][1], (float)acc[ni][1], bb[ni][1]), 0.f, 6.f);
            float v2 = clampf(fmaf(af[ni][0], (float)acc[ni][2], bb[ni][0]), 0.f, 6.f);
            float v3 = clampf(fmaf(af[ni][1], (float)acc[ni][3], bb[ni][1]), 0.f, 6.f);
            y1b[ c0   *788 + px0] = (int8_t)(int)fminf(rintf(v0*inv1), 127.f);
            y1b[(c0+1)*788 + px0] = (int8_t)(int)fminf(rintf(v1*inv1), 127.f);
            y1b[ c0   *788 + px1] = (int8_t)(int)fminf(rintf(v2*inv1), 127.f);
            y1b[(c0+1)*788 + px1] = (int8_t)(int)fminf(rintf(v3*inv1), 127.f);
        }
    }
    __syncthreads();

    float inv2 = 1.0f / g_s[2];
    int8_t* y2b = (int8_t*)y2;
    for (int task=t; task<64*28; task+=256){
        int c = task & 63, h = task >> 6;
        int cg = ch*64 + c;
        uint32_t wk0 = g_w2q[cg*3+0], wk1 = g_w2q[cg*3+1], wk2 = g_w2q[cg*3+2];
        float a2 = g_a2[cg], b2 = g_bb2[cg];
        const uint32_t* rw = y1 + c*Y1W;
        uint32_t rm[7], rc[7], rp[7];
        #pragma unroll
        for (int j=0;j<7;j++){
            rc[j] = rw[h*7 + j];
            rm[j] = (h > 0)  ? rw[(h-1)*7 + j] : 0u;
            rp[j] = (h < 27) ? rw[(h+1)*7 + j] : 0u;
        }
        uint32_t pm=0, pc=0, pp=0;
        #pragma unroll
        for (int j=0;j<7;j++){
            uint32_t nm = (j<6)? rm[j+1] : 0u;
            uint32_t nc = (j<6)? rc[j+1] : 0u;
            uint32_t np = (j<6)? rp[j+1] : 0u;
            int o0 = __dp4a((int)__byte_perm(pm, rm[j], 0x6543), (int)wk0, 0)
                   + __dp4a((int)__byte_perm(pc, rc[j], 0x6543), (int)wk1, 0)
                   + __dp4a((int)__byte_perm(pp, rp[j], 0x6543), (int)wk2, 0);
            int o1 = __dp4a((int)rm[j], (int)wk0, 0)
                   + __dp4a((int)rc[j], (int)wk1, 0)
                   + __dp4a((int)rp[j], (int)wk2, 0);
            int o2 = __dp4a((int)__byte_perm(rm[j], nm, 0x4321), (int)wk0, 0)
                   + __dp4a((int)__byte_perm(rc[j], nc, 0x4321), (int)wk1, 0)
                   + __dp4a((int)__byte_perm(rp[j], np, 0x4321), (int)wk2, 0);
            int o3 = __dp4a((int)__byte_perm(rm[j], nm, 0x5432), (int)wk0, 0)
                   + __dp4a((int)__byte_perm(rc[j], nc, 0x5432), (int)wk1, 0)
                   + __dp4a((int)__byte_perm(rp[j], np, 0x5432), (int)wk2, 0);
            int outs[4] = {o0, o1, o2, o3};
            #pragma unroll
            for (int i2=0;i2<4;i2++){
                float y = clampf(fmaf(a2, (float)outs[i2], b2), 0.f, 6.f);
                int q = (int)fminf(rintf(y*inv2), 127.f);
                y2b[(h*28 + j*4 + i2)*64 + c] = (int8_t)q;
            }
            pm = rm[j]; pc = rc[j]; pp = rp[j];
        }
    }
    __syncthreads();

    uint32_t* dst = g_y2q + (size_t)img*HWp*KW3 + ch*16;
    for (int i=t; i<HWp*4; i+=256){
        int p = i>>2, q = i&3;
        *(uint4*)&dst[(size_t)p*KW3 + q*4] = ((const uint4*)y2)[i];
    }
}

// ---------------- conv3 v2: 128px x 96ch tile, 256 threads, 8 warps ----------------
#define SB3 148
#define SO3 101
#define SM3_WORDS ((CIN + 128)*SB3)    // 224*148 = 33152 words
#define SM3_BYTES (SM3_WORDS*4)        // 132608
__global__ __launch_bounds__(256) void k_conv3(const float* __restrict__ x,
                                               float* __restrict__ out, int out_size){
    extern __shared__ __align__(16) uint32_t sm[];
    uint32_t* sB = sm;               // 96 x 148
    uint32_t* sA = sm + CIN*SB3;     // 128 x 148
    int t = threadIdx.x;
    int p0 = blockIdx.x*128;
    for (int i=t; i<CIN*36; i+=256){
        int r = i/36, q = i%36;
        *(uint4*)&sB[r*SB3 + q*4] = *(const uint4*)&g_w3q[r*KW3 + q*4];
    }
    const uint32_t* A = g_y2q + (size_t)p0*KW3;
    for (int i=t; i<128*36; i+=256){
        int r = i/36, q = i%36;
        *(uint4*)&sA[r*SB3 + q*4] = *(const uint4*)&A[r*KW3 + q*4];
    }
    __syncthreads();
    int lane = t & 31, warp = t >> 5, r4 = lane >> 2, w4 = lane & 3;
    int m0 = (warp & 3)*32, n0 = (warp >> 2)*48;
    int acc[2][6][4] = {};
    #pragma unroll 2
    for (int ks=0; ks<18; ks++){
        uint32_t a[2][4], b[6][2];
        #pragma unroll
        for (int mi=0; mi<2; mi++){
            int rb = (m0 + mi*16 + r4)*SB3 + ks*8 + w4;
            a[mi][0] = sA[rb];       a[mi][1] = sA[rb + 8*SB3];
            a[mi][2] = sA[rb + 4];   a[mi][3] = sA[rb + 8*SB3 + 4];
        }
        #pragma unroll
        for (int ni=0; ni<6; ni++){
            int nb = (n0 + ni*8 + r4)*SB3 + ks*8 + w4;
            b[ni][0] = sB[nb];  b[ni][1] = sB[nb + 4];
        }
        #pragma unroll
        for (int mi=0; mi<2; mi++)
            #pragma unroll
            for (int ni=0; ni<6; ni++)
                imma(acc[mi][ni][0],acc[mi][ni][1],acc[mi][ni][2],acc[mi][ni][3],
                     a[mi][0],a[mi][1],a[mi][2],a[mi][3], b[ni][0],b[ni][1]);
    }
    __syncthreads();
    float* sO = (float*)sm;   // 128 x 101 floats = 51.7 KB
    #pragma unroll
    for (int ni=0; ni<6; ni++){
        int c = n0 + ni*8 + 2*w4;
        float af0 = g_a3[c],  af1 = g_a3[c+1];
        float bf0 = g_bb3[c], bf1 = g_bb3[c+1];
        #pragma unroll
        for (int mi=0; mi<2; mi++){
            int row0 = m0 + mi*16 + r4;
            sO[ row0   *SO3 + c    ] = fmaf(af0, (float)acc[mi][ni][0], bf0);
            sO[ row0   *SO3 + c + 1] = fmaf(af1, (float)acc[mi][ni][1], bf1);
            sO[(row0+8)*SO3 + c    ] = fmaf(af0, (float)acc[mi][ni][2], bf0);
            sO[(row0+8)*SO3 + c + 1] = fmaf(af1, (float)acc[mi][ni][3], bf1);
        }
    }
    __syncthreads();
    float s3 = g_s[3];
    float inv3 = 1.0f / s3;
    for (int idx=t; idx<CIN*128; idx+=256){
        int c = idx >> 7, pl = idx & 127;
        int p = p0 + pl;
        int b = p / HWp, hw = p % HWp;
        size_t g = (size_t)b*CIN*HWp + (size_t)c*HWp + hw;
        float y = sO[pl*SO3 + c] + x[g];
        float q = clampf(rintf(y*inv3), -127.f, 127.f);
        out[g] = q * s3;
    }
    if (blockIdx.x == 0){
        for (int i = OUT_ELEMS + t; i < out_size; i += 256) out[i] = g_s[3];
    }
}

// ---------------- launch ----------------
extern "C" void kernel_launch(void* const* d_in, const int* in_sizes, int n_in,
                              void* d_out, int out_size){
    const float* x  = (const float*)d_in[0];
    const float* w1 = (const float*)d_in[1];
    const float* g1 = (const float*)d_in[2];
    const float* b1 = (const float*)d_in[3];
    const float* m1 = (const float*)d_in[4];
    const float* v1 = (const float*)d_in[5];
    const float* w2 = (const float*)d_in[6];
    const float* g2 = (const float*)d_in[7];
    const float* b2 = (const float*)d_in[8];
    const float* m2 = (const float*)d_in[9];
    const float* v2 = (const float*)d_in[10];
    const float* w3 = (const float*)d_in[11];
    const float* g3 = (const float*)d_in[12];
    const float* b3 = (const float*)d_in[13];
    const float* m3 = (const float*)d_in[14];
    const float* v3 = (const float*)d_in[15];
    const float* r0 = (const float*)d_in[16];
    const float* r1 = (const float*)d_in[17];
    const float* r2 = (const float*)d_in[18];
    const float* r3 = (const float*)d_in[19];
    const int*   cl = (const int*)d_in[20];

    cudaFuncSetAttribute(k_c1dw,  cudaFuncAttributeMaxDynamicSharedMemorySize, SM1_BYTES);
    cudaFuncSetAttribute(k_conv3, cudaFuncAttributeMaxDynamicSharedMemorySize, SM3_BYTES);

    k_prep<<<CMID + 9 + CIN, 192>>>(w1,g1,b1,m1,v1, w2,g2,b2,m2,v2, w3,g3,b3,m3,v3,
                                    r0,r1,r2,r3, cl);
    k_qx<<<NPIX/128, 128>>>(x);
    k_c1dw<<<dim3(9, NB), 256, SM1_BYTES>>>();
    k_conv3<<<NPIX/128, 256, SM3_BYTES>>>(x, (float*)d_out, out_size);
}

// round 10
// speedup vs baseline: 2.7209x; 1.4164x over previous
#include <cuda_runtime.h>
#include <stdint.h>

#define NB   64
#define CIN  96
#define HWp  784
#define CMID 576
#define NPIX (NB*HWp)          // 50176
#define KW1  24                // 96/4
#define KW3  144               // 576/4
#define OUT_ELEMS (NB*CIN*HWp) // 4816896

// ---------------- device scratch ----------------
__device__ float    g_s[4];
__device__ uint32_t g_xq [NPIX*KW1];
__device__ uint32_t g_y2q[NPIX*KW3];
__device__ uint32_t g_w1q[CMID*KW1];
__device__ uint32_t g_w2q[CMID*3];     // per channel: 3 row-words (k0,k1,k2,0)
__device__ uint32_t g_w3q[CIN*KW3];
__device__ float g_a1[CMID], g_bb1[CMID];
__device__ float g_a2[CMID], g_bb2[CMID];
__device__ float g_a3[CIN],  g_bb3[CIN];

__device__ __forceinline__ float clampf(float v, float lo, float hi){ return fminf(fmaxf(v,lo),hi); }

__device__ __forceinline__ void imma(int& d0,int& d1,int& d2,int& d3,
                                     uint32_t a0,uint32_t a1,uint32_t a2,uint32_t a3,
                                     uint32_t b0,uint32_t b1){
    asm volatile("mma.sync.aligned.m16n8k32.row.col.s32.s8.s8.s32 "
                 "{%0,%1,%2,%3},{%4,%5,%6,%7},{%8,%9},{%0,%1,%2,%3};"
                 : "+r"(d0),"+r"(d1),"+r"(d2),"+r"(d3)
                 : "r"(a0),"r"(a1),"r"(a2),"r"(a3),"r"(b0),"r"(b1));
}
__device__ __forceinline__ void ldm_x4(uint32_t& r0,uint32_t& r1,uint32_t& r2,uint32_t& r3,
                                       uint32_t addr){
    asm volatile("ldmatrix.sync.aligned.m8n8.x4.shared.b16 {%0,%1,%2,%3}, [%4];"
                 : "=r"(r0),"=r"(r1),"=r"(r2),"=r"(r3) : "r"(addr));
}
__device__ __forceinline__ void cpa16(uint32_t dst, const void* src){
    asm volatile("cp.async.cg.shared.global [%0], [%1], 16;" :: "r"(dst), "l"(src));
}
__device__ __forceinline__ void cpa16z(uint32_t dst, const void* src, uint32_t nsrc){
    asm volatile("cp.async.cg.shared.global [%0], [%1], 16, %2;" :: "r"(dst), "l"(src), "r"(nsrc));
}
__device__ __forceinline__ void cp_commit_wait(){
    asm volatile("cp.async.commit_group;");
    asm volatile("cp.async.wait_group 0;");
}
__device__ __forceinline__ uint32_t smem_u32(const void* p){
    uint32_t a;
    asm("{ .reg .u64 t; cvta.to.shared.u64 t, %1; cvt.u32.u64 %0, t; }" : "=r"(a) : "l"(p));
    return a;
}

// ---------------- single prep kernel: 681 blocks ----------------
__global__ __launch_bounds__(192) void k_prep(
    const float* __restrict__ w1, const float* __restrict__ g1, const float* __restrict__ b1,
    const float* __restrict__ m1, const float* __restrict__ v1,
    const float* __restrict__ w2, const float* __restrict__ g2, const float* __restrict__ b2,
    const float* __restrict__ m2, const float* __restrict__ v2,
    const float* __restrict__ w3, const float* __restrict__ g3, const float* __restrict__ b3,
    const float* __restrict__ m3, const float* __restrict__ v3,
    const float* __restrict__ r0, const float* __restrict__ r1,
    const float* __restrict__ r2, const float* __restrict__ r3,
    const int* __restrict__ cl_)
{
    __shared__ float red[6];
    int bid = blockIdx.x, t = threadIdx.x;
    int cl = cl_[0];
    if (bid == 0 && t == 0){
        g_s[0]=r0[cl]/127.0f; g_s[1]=r1[cl]/127.0f;
        g_s[2]=r2[cl]/127.0f; g_s[3]=r3[cl]/127.0f;
    }
    if (bid < CMID){
        int o = bid;
        float sc = g1[o] * rsqrtf(v1[o] + 1e-5f);
        float wf = 0.f;
        if (t < 96) wf = w1[o*CIN + t] * sc;
        float amx = fabsf(wf);
        #pragma unroll
        for (int off=16; off; off>>=1) amx = fmaxf(amx, __shfl_xor_sync(0xffffffffu, amx, off));
        if ((t & 31) == 0) red[t>>5] = amx;
        __syncthreads();
        float mx = red[0];
        #pragma unroll
        for (int i=1;i<6;i++) mx = fmaxf(mx, red[i]);
        float sw = mx / 127.0f;
        if (t < 96){
            float q = clampf(rintf(wf / sw), -127.f, 127.f);
            ((int8_t*)g_w1q)[o*CIN + t] = (int8_t)q;
        }
        if (t == 0){
            float s0 = r0[cl]/127.0f;
            g_a1[o] = s0*sw; g_bb1[o] = b1[o] - m1[o]*sc;
        }
    } else if (bid < CMID + 9){
        if (t < 64){
            int c = (bid - CMID)*64 + t;
            float sc = g2[c] * rsqrtf(v2[c] + 1e-5f);
            float wf[9]; float mx = 0.f;
            #pragma unroll
            for (int j=0;j<9;j++){ wf[j] = w2[c*9+j]*sc; mx = fmaxf(mx, fabsf(wf[j])); }
            float sw = mx / 127.0f;
            #pragma unroll
            for (int dh=0; dh<3; dh++){
                uint32_t pk = 0;
                #pragma unroll
                for (int dw=0; dw<3; dw++){
                    int q = (int)clampf(rintf(wf[dh*3+dw]/sw), -127.f, 127.f);
                    pk |= ((uint32_t)(uint8_t)(int8_t)q) << (8*dw);
                }
                g_w2q[c*3 + dh] = pk;
            }
            float s1 = r1[cl]/127.0f;
            g_a2[c] = s1*sw; g_bb2[c] = b2[c] - m2[c]*sc;
        }
    } else {
        int o = bid - (CMID + 9);
        float sc = g3[o] * rsqrtf(v3[o] + 1e-5f);
        float f0 = w3[o*CMID + t      ]*sc;
        float f1 = w3[o*CMID + t + 192]*sc;
        float f2 = w3[o*CMID + t + 384]*sc;
        float amx = fmaxf(fabsf(f0), fmaxf(fabsf(f1), fabsf(f2)));
        #pragma unroll
        for (int off=16; off; off>>=1) amx = fmaxf(amx, __shfl_xor_sync(0xffffffffu, amx, off));
        if ((t & 31) == 0) red[t>>5] = amx;
        __syncthreads();
        float mx = red[0];
        #pragma unroll
        for (int i=1;i<6;i++) mx = fmaxf(mx, red[i]);
        float sw = mx / 127.0f;
        int8_t* dst = (int8_t*)g_w3q + o*CMID;
        dst[t      ] = (int8_t)clampf(rintf(f0/sw), -127.f, 127.f);
        dst[t + 192] = (int8_t)clampf(rintf(f1/sw), -127.f, 127.f);
        dst[t + 384] = (int8_t)clampf(rintf(f2/sw), -127.f, 127.f);
        if (t == 0){
            float s2 = r2[cl]/127.0f;
            g_a3[o] = s2*sw; g_bb3[o] = b3[o] - m3[o]*sc;
        }
    }
}

// ---------------- stage 0: quantize x ----------------
__global__ __launch_bounds__(128) void k_qx(const float* __restrict__ x){
    __shared__ int8_t sq[CIN*128];
    int t  = threadIdx.x;
    int p0 = blockIdx.x*128;
    int p  = p0 + t;
    int b  = p / HWp, hw = p % HWp;
    const float* xb = x + (size_t)b*CIN*HWp + hw;
    float inv0 = 1.0f / g_s[0];
    #pragma unroll 4
    for (int c=0;c<CIN;c++){
        float q = clampf(rintf(xb[(size_t)c*HWp] * inv0), -127.f, 127.f);
        sq[c*128 + t] = (int8_t)q;
    }
    __syncthreads();
    uint32_t* ow = g_xq + (size_t)p0*KW1;
    for (int w=t; w<128*KW1; w+=128){
        int pl = w / KW1;
        int c0 = (w % KW1)*4;
        uint32_t v =  (uint32_t)(uint8_t)sq[(c0+0)*128+pl]
                   | ((uint32_t)(uint8_t)sq[(c0+1)*128+pl] << 8)
                   | ((uint32_t)(uint8_t)sq[(c0+2)*128+pl] << 16)
                   | ((uint32_t)(uint8_t)sq[(c0+3)*128+pl] << 24);
        ow[w] = v;
    }
}

// ---------------- fused conv1 + depthwise, half-image blocks ----------------
// block = (ch chunk 0..8, img, half 0..1). Slab = 16 rows (1 halo each side) x 28 = 448 px.
#define SAW  28            // A smem stride (words)
#define SPX  448
#define Y1S  113           // y1 stride per channel (words); 452 bytes
#define D_OFF_W  (SPX*SAW)                 // 12544
#define D_OFF_Y1 (D_OFF_W + 64*SAW)        // 14336
#define D_OFF_SC (D_OFF_Y1 + 64*Y1S)       // 21568
#define D_WORDS  (D_OFF_SC + 128)          // 21696
#define D_BYTES  (D_WORDS*4)               // 86784
__global__ __launch_bounds__(256,2) void k_c1dw(){
    extern __shared__ __align__(16) uint32_t sm[];
    uint32_t* sW = sm + D_OFF_W;
    uint32_t* y1 = sm + D_OFF_Y1;
    float* sAf = (float*)(sm + D_OFF_SC);
    float* sBf = (float*)(sm + D_OFF_SC + 64);
    int t    = threadIdx.x;
    int ch   = blockIdx.x;
    int img  = blockIdx.y;
    int half = blockIdx.z;
    int off  = half*392 - 28;       // slab px -> image px offset
    uint32_t sbase = smem_u32(sm);

    if (t < 64){ sAf[t] = g_a1[ch*64+t]; sBf[t] = g_bb1[ch*64+t]; }
    const uint32_t* Aim = g_xq + (size_t)img*HWp*KW1;
    for (int i=t; i<SPX*6; i+=256){
        int sp = i/6, q = i%6;
        int ip = sp + off;
        uint32_t v = ((unsigned)ip < (unsigned)HWp) ? 16u : 0u;
        cpa16z(sbase + (uint32_t)(sp*SAW + q*4)*4, &Aim[(v? ip:0)*KW1 + q*4], v);
    }
    for (int i=t; i<64*6; i+=256){
        int r = i/6, q = i%6;
        cpa16(sbase + (uint32_t)(D_OFF_W + r*SAW + q*4)*4, &g_w1q[(ch*64+r)*KW1 + q*4]);
    }
    cp_commit_wait();
    __syncthreads();

    int lane = t & 31, warp = t >> 5, r4 = lane >> 2, w4 = lane & 3;
    uint32_t bf[3][8][2];
    #pragma unroll
    for (int kc=0;kc<3;kc++)
        #pragma unroll
        for (int ni=0;ni<8;ni++){
            int rb = (ni*8 + r4)*SAW + kc*8 + w4;
            bf[kc][ni][0] = sW[rb]; bf[kc][ni][1] = sW[rb+4];
        }
    float inv1 = 1.0f / g_s[1];
    int8_t* y1b = (int8_t*)y1;
    uint32_t aLane = sbase + ((lane&7) + ((lane>>3)&1)*8)*112 + ((lane>>4)&1)*16;

    for (int tile = warp; tile < 28; tile += 8){
        int m0 = tile*16;
        int acc[8][4] = {};
        #pragma unroll
        for (int kc=0;kc<3;kc++){
            uint32_t a0,a1,a2,a3;
            ldm_x4(a0,a1,a2,a3, aLane + (uint32_t)(m0*112 + kc*32));
            #pragma unroll
            for (int ni=0;ni<8;ni++)
                imma(acc[ni][0],acc[ni][1],acc[ni][2],acc[ni][3],
                     a0,a1,a2,a3, bf[kc][ni][0], bf[kc][ni][1]);
        }
        int px0 = m0 + r4, px1 = px0 + 8;
        bool v0 = (unsigned)(px0 + off) < (unsigned)HWp;
        bool v1 = (unsigned)(px1 + off) < (unsigned)HWp;
        #pragma unroll
        for (int ni=0;ni<8;ni++){
            int c0 = ni*8 + 2*w4;
            float af0 = sAf[c0], af1 = sAf[c0+1];
            float bb0 = sBf[c0], bb1 = sBf[c0+1];
            float q0 = fminf(rintf(clampf(fmaf(af0,(float)acc[ni][0],bb0),0.f,6.f)*inv1),127.f);
            float q1 = fminf(rintf(clampf(fmaf(af1,(float)acc[ni][1],bb1),0.f,6.f)*inv1),127.f);
            float q2 = fminf(rintf(clampf(fmaf(af0,(float)acc[ni][2],bb0),0.f,6.f)*inv1),127.f);
            float q3 = fminf(rintf(clampf(fmaf(af1,(float)acc[ni][3],bb1),0.f,6.f)*inv1),127.f);
            y1b[ c0   *452 + px0] = v0 ? (int8_t)(int)q0 : (int8_t)0;
            y1b[(c0+1)*452 + px0] = v0 ? (int8_t)(int)q1 : (int8_t)0;
            y1b[ c0   *452 + px1] = v1 ? (int8_t)(int)q2 : (int8_t)0;
            y1b[(c0+1)*452 + px1] = v1 ? (int8_t)(int)q3 : (int8_t)0;
        }
    }
    __syncthreads();

    // depthwise: output rows j=0..13 use y1 slab rows j, j+1, j+2 (zeros at image edges)
    float inv2 = 1.0f / g_s[2];
    int8_t* y2b = (int8_t*)sm;     // alias over sA (free after MMA)
    for (int task=t; task<64*14; task+=256){
        int c = task & 63, j = task >> 6;
        int cg = ch*64 + c;
        uint32_t wk0 = g_w2q[cg*3+0], wk1 = g_w2q[cg*3+1], wk2 = g_w2q[cg*3+2];
        float a2 = g_a2[cg], b2 = g_bb2[cg];
        const uint32_t* rw = y1 + c*Y1S;
        uint32_t rm[7], rc[7], rp[7];
        #pragma unroll
        for (int q=0;q<7;q++){
            rm[q] = rw[ j   *7 + q];
            rc[q] = rw[(j+1)*7 + q];
            rp[q] = rw[(j+2)*7 + q];
        }
        uint32_t pm=0, pc=0, pp=0;
        #pragma unroll
        for (int w=0; w<7; w++){
            uint32_t nm = (w<6)? rm[w+1] : 0u;
            uint32_t nc = (w<6)? rc[w+1] : 0u;
            uint32_t np = (w<6)? rp[w+1] : 0u;
            int o0 = __dp4a((int)__byte_perm(pm, rm[w], 0x6543), (int)wk0, 0)
                   + __dp4a((int)__byte_perm(pc, rc[w], 0x6543), (int)wk1, 0)
                   + __dp4a((int)__byte_perm(pp, rp[w], 0x6543), (int)wk2, 0);
            int o1 = __dp4a((int)rm[w], (int)wk0, 0)
                   + __dp4a((int)rc[w], (int)wk1, 0)
                   + __dp4a((int)rp[w], (int)wk2, 0);
            int o2 = __dp4a((int)__byte_perm(rm[w], nm, 0x4321), (int)wk0, 0)
                   + __dp4a((int)__byte_perm(rc[w], nc, 0x4321), (int)wk1, 0)
                   + __dp4a((int)__byte_perm(rp[w], np, 0x4321), (int)wk2, 0);
            int o3 = __dp4a((int)__byte_perm(rm[w], nm, 0x5432), (int)wk0, 0)
                   + __dp4a((int)__byte_perm(rc[w], nc, 0x5432), (int)wk1, 0)
                   + __dp4a((int)__byte_perm(rp[w], np, 0x5432), (int)wk2, 0);
            int outs[4] = {o0, o1, o2, o3};
            #pragma unroll
            for (int i2=0;i2<4;i2++){
                float y = clampf(fmaf(a2, (float)outs[i2], b2), 0.f, 6.f);
                int q = (int)fminf(rintf(y*inv2), 127.f);
                y2b[(j*28 + w*4 + i2)*64 + c] = (int8_t)q;
            }
            pm = rm[w]; pc = rc[w]; pp = rp[w];
        }
    }
    __syncthreads();

    uint32_t* dst = g_y2q + ((size_t)img*HWp + half*392)*KW3 + ch*16;
    const uint32_t* y2w = sm;
    for (int i=t; i<392*4; i+=256){
        int p = i>>2, q = i&3;
        *(uint4*)&dst[(size_t)p*KW3 + q*4] = *(const uint4*)&y2w[p*16 + q*4];
    }
}

// ---------------- conv3: 64px x 96ch, 256 thr, 2 CTA/SM, ldmatrix ----------------
#define SB3 148
#define C3_B  192                     // after 192 words of scale cache
#define C3_A  (C3_B + CIN*SB3)        // 192 + 14208 = 14400
#define C3_WORDS (C3_A + 64*SB3)      // + 9472 = 23872
#define C3_BYTES (C3_WORDS*4)         // 95488
#define SO3 101
__global__ __launch_bounds__(256,2) void k_conv3(const float* __restrict__ x,
                                                 float* __restrict__ out, int out_size){
    extern __shared__ __align__(16) uint32_t sm[];
    float* sa3 = (float*)sm;          // 96
    float* sb3 = (float*)(sm + 96);   // 96
    int t = threadIdx.x;
    int p0 = blockIdx.x*64;
    uint32_t sbase = smem_u32(sm);

    if (t < 96){ sa3[t] = g_a3[t]; sb3[t] = g_bb3[t]; }
    for (int i=t; i<CIN*36; i+=256){
        int r = i/36, q = i%36;
        cpa16(sbase + (uint32_t)(C3_B + r*SB3 + q*4)*4, &g_w3q[r*KW3 + q*4]);
    }
    const uint32_t* Ag = g_y2q + (size_t)p0*KW3;
    for (int i=t; i<64*36; i+=256){
        int r = i/36, q = i%36;
        cpa16(sbase + (uint32_t)(C3_A + r*SB3 + q*4)*4, &Ag[r*KW3 + q*4]);
    }
    cp_commit_wait();
    __syncthreads();

    int lane = t & 31, warp = t >> 5, r4 = lane >> 2, w4 = lane & 3;
    int m0 = (warp & 3)*16, n0 = (warp >> 2)*48;
    uint32_t aBase = sbase + (uint32_t)C3_A*4
                   + (uint32_t)(m0 + (lane&7) + ((lane>>3)&1)*8)*592 + ((lane>>4)&1)*16;
    uint32_t bBase = sbase + (uint32_t)C3_B*4
                   + (uint32_t)(n0 + (lane&7) + ((lane>>4)&1)*8)*592 + ((lane>>3)&1)*16;
    int acc[6][4] = {};
    #pragma unroll 3
    for (int ks=0; ks<18; ks++){
        uint32_t a0,a1,a2,a3;
        ldm_x4(a0,a1,a2,a3, aBase + (uint32_t)ks*32);
        #pragma unroll
        for (int tp=0; tp<3; tp++){
            uint32_t b0,b1,b2,b3;
            ldm_x4(b0,b1,b2,b3, bBase + (uint32_t)(tp*16*592) + (uint32_t)ks*32);
            imma(acc[2*tp  ][0],acc[2*tp  ][1],acc[2*tp  ][2],acc[2*tp  ][3],
                 a0,a1,a2,a3, b0,b1);
            imma(acc[2*tp+1][0],acc[2*tp+1][1],acc[2*tp+1][2],acc[2*tp+1][3],
                 a0,a1,a2,a3, b2,b3);
        }
    }
    __syncthreads();
    float* sO = (float*)(sm + C3_A);   // 64 x 101 floats = 25856 B (fits in sA region)
    #pragma unroll
    for (int ni=0; ni<6; ni++){
        int c = n0 + ni*8 + 2*w4;
        float af0 = sa3[c],  af1 = sa3[c+1];
        float bf0 = sb3[c],  bf1 = sb3[c+1];
        int row0 = m0 + r4;
        sO[ row0   *SO3 + c    ] = fmaf(af0, (float)acc[ni][0], bf0);
        sO[ row0   *SO3 + c + 1] = fmaf(af1, (float)acc[ni][1], bf1);
        sO[(row0+8)*SO3 + c    ] = fmaf(af0, (float)acc[ni][2], bf0);
        sO[(row0+8)*SO3 + c + 1] = fmaf(af1, (float)acc[ni][3], bf1);
    }
    __syncthreads();
    float s3 = g_s[3];
    float inv3 = 1.0f / s3;
    for (int idx=t; idx<CIN*64; idx+=256){
        int c = idx >> 6, pl = idx & 63;
        int p = p0 + pl;
        int b = p / HWp, hw = p % HWp;
        size_t g = (size_t)b*CIN*HWp + (size_t)c*HWp + hw;
        float y = sO[pl*SO3 + c] + x[g];
        float q = clampf(rintf(y*inv3), -127.f, 127.f);
        out[g] = q * s3;
    }
    if (blockIdx.x == 0){
        for (int i = OUT_ELEMS + t; i < out_size; i += 256) out[i] = g_s[3];
    }
}

// ---------------- launch ----------------
extern "C" void kernel_launch(void* const* d_in, const int* in_sizes, int n_in,
                              void* d_out, int out_size){
    const float* x  = (const float*)d_in[0];
    const float* w1 = (const float*)d_in[1];
    const float* g1 = (const float*)d_in[2];
    const float* b1 = (const float*)d_in[3];
    const float* m1 = (const float*)d_in[4];
    const float* v1 = (const float*)d_in[5];
    const float* w2 = (const float*)d_in[6];
    const float* g2 = (const float*)d_in[7];
    const float* b2 = (const float*)d_in[8];
    const float* m2 = (const float*)d_in[9];
    const float* v2 = (const float*)d_in[10];
    const float* w3 = (const float*)d_in[11];
    const float* g3 = (const float*)d_in[12];
    const float* b3 = (const float*)d_in[13];
    const float* m3 = (const float*)d_in[14];
    const float* v3 = (const float*)d_in[15];
    const float* r0 = (const float*)d_in[16];
    const float* r1 = (const float*)d_in[17];
    const float* r2 = (const float*)d_in[18];
    const float* r3 = (const float*)d_in[19];
    const int*   cl = (const int*)d_in[20];

    cudaFuncSetAttribute(k_c1dw,  cudaFuncAttributeMaxDynamicSharedMemorySize, D_BYTES);
    cudaFuncSetAttribute(k_conv3, cudaFuncAttributeMaxDynamicSharedMemorySize, C3_BYTES);

    k_prep<<<CMID + 9 + CIN, 192>>>(w1,g1,b1,m1,v1, w2,g2,b2,m2,v2, w3,g3,b3,m3,v3,
                                    r0,r1,r2,r3, cl);
    k_qx<<<NPIX/128, 128>>>(x);
    k_c1dw<<<dim3(9, NB, 2), 256, D_BYTES>>>();
    k_conv3<<<NPIX/64, 256, C3_BYTES>>>(x, (float*)d_out, out_size);
}

// round 12
// speedup vs baseline: 2.7708x; 1.0183x over previous
#include <cuda_runtime.h>
#include <stdint.h>

#define NB   64
#define CIN  96
#define HWp  784
#define CMID 576
#define NPIX (NB*HWp)          // 50176
#define KW1  24                // 96/4
#define KW3  144               // 576/4
#define OUT_ELEMS (NB*CIN*HWp) // 4816896

// ---------------- device scratch ----------------
__device__ float    g_s[4];
__device__ uint32_t g_xq [NPIX*KW1];
__device__ uint32_t g_y2q[NPIX*KW3];
__device__ uint32_t g_w1q[CMID*KW1];
__device__ uint32_t g_w2q[CMID*3];     // per channel: 3 row-words (k0,k1,k2,0)
__device__ uint32_t g_w3q[CIN*KW3];
__device__ float g_a1[CMID], g_bb1[CMID];
__device__ float g_a2[CMID], g_bb2[CMID];
__device__ float g_a3[CIN],  g_bb3[CIN];

__device__ __forceinline__ float clampf(float v, float lo, float hi){ return fminf(fmaxf(v,lo),hi); }

__device__ __forceinline__ void imma(int& d0,int& d1,int& d2,int& d3,
                                     uint32_t a0,uint32_t a1,uint32_t a2,uint32_t a3,
                                     uint32_t b0,uint32_t b1){
    asm volatile("mma.sync.aligned.m16n8k32.row.col.s32.s8.s8.s32 "
                 "{%0,%1,%2,%3},{%4,%5,%6,%7},{%8,%9},{%0,%1,%2,%3};"
                 : "+r"(d0),"+r"(d1),"+r"(d2),"+r"(d3)
                 : "r"(a0),"r"(a1),"r"(a2),"r"(a3),"r"(b0),"r"(b1));
}
__device__ __forceinline__ void ldm_x4(uint32_t& r0,uint32_t& r1,uint32_t& r2,uint32_t& r3,
                                       uint32_t addr){
    asm volatile("ldmatrix.sync.aligned.m8n8.x4.shared.b16 {%0,%1,%2,%3}, [%4];"
                 : "=r"(r0),"=r"(r1),"=r"(r2),"=r"(r3) : "r"(addr));
}
__device__ __forceinline__ void ldm_x2(uint32_t& r0,uint32_t& r1, uint32_t addr){
    asm volatile("ldmatrix.sync.aligned.m8n8.x2.shared.b16 {%0,%1}, [%2];"
                 : "=r"(r0),"=r"(r1) : "r"(addr));
}
__device__ __forceinline__ void cpa16(uint32_t dst, const void* src){
    asm volatile("cp.async.cg.shared.global [%0], [%1], 16;" :: "r"(dst), "l"(src));
}
__device__ __forceinline__ void cpa16z(uint32_t dst, const void* src, uint32_t nsrc){
    asm volatile("cp.async.cg.shared.global [%0], [%1], 16, %2;" :: "r"(dst), "l"(src), "r"(nsrc));
}
__device__ __forceinline__ void cp_commit_wait(){
    asm volatile("cp.async.commit_group;");
    asm volatile("cp.async.wait_group 0;");
}
__device__ __forceinline__ uint32_t smem_u32(const void* p){
    uint32_t a;
    asm("{ .reg .u64 t; cvta.to.shared.u64 t, %1; cvt.u32.u64 %0, t; }" : "=r"(a) : "l"(p));
    return a;
}

// ---------------- single prep kernel: 681 blocks ----------------
__global__ __launch_bounds__(192) void k_prep(
    const float* __restrict__ w1, const float* __restrict__ g1, const float* __restrict__ b1,
    const float* __restrict__ m1, const float* __restrict__ v1,
    const float* __restrict__ w2, const float* __restrict__ g2, const float* __restrict__ b2,
    const float* __restrict__ m2, const float* __restrict__ v2,
    const float* __restrict__ w3, const float* __restrict__ g3, const float* __restrict__ b3,
    const float* __restrict__ m3, const float* __restrict__ v3,
    const float* __restrict__ r0, const float* __restrict__ r1,
    const float* __restrict__ r2, const float* __restrict__ r3,
    const int* __restrict__ cl_)
{
    __shared__ float red[6];
    int bid = blockIdx.x, t = threadIdx.x;
    int cl = cl_[0];
    if (bid == 0 && t == 0){
        g_s[0]=r0[cl]/127.0f; g_s[1]=r1[cl]/127.0f;
        g_s[2]=r2[cl]/127.0f; g_s[3]=r3[cl]/127.0f;
    }
    if (bid < CMID){
        int o = bid;
        float sc = g1[o] * rsqrtf(v1[o] + 1e-5f);
        float wf = 0.f;
        if (t < 96) wf = w1[o*CIN + t] * sc;
        float amx = fabsf(wf);
        #pragma unroll
        for (int off=16; off; off>>=1) amx = fmaxf(amx, __shfl_xor_sync(0xffffffffu, amx, off));
        if ((t & 31) == 0) red[t>>5] = amx;
        __syncthreads();
        float mx = red[0];
        #pragma unroll
        for (int i=1;i<6;i++) mx = fmaxf(mx, red[i]);
        float sw = mx / 127.0f;
        if (t < 96){
            float q = clampf(rintf(wf / sw), -127.f, 127.f);
            ((int8_t*)g_w1q)[o*CIN + t] = (int8_t)q;
        }
        if (t == 0){
            float s0 = r0[cl]/127.0f;
            g_a1[o] = s0*sw; g_bb1[o] = b1[o] - m1[o]*sc;
        }
    } else if (bid < CMID + 9){
        if (t < 64){
            int c = (bid - CMID)*64 + t;
            float sc = g2[c] * rsqrtf(v2[c] + 1e-5f);
            float wf[9]; float mx = 0.f;
            #pragma unroll
            for (int j=0;j<9;j++){ wf[j] = w2[c*9+j]*sc; mx = fmaxf(mx, fabsf(wf[j])); }
            float sw = mx / 127.0f;
            #pragma unroll
            for (int dh=0; dh<3; dh++){
                uint32_t pk = 0;
                #pragma unroll
                for (int dw=0; dw<3; dw++){
                    int q = (int)clampf(rintf(wf[dh*3+dw]/sw), -127.f, 127.f);
                    pk |= ((uint32_t)(uint8_t)(int8_t)q) << (8*dw);
                }
                g_w2q[c*3 + dh] = pk;
            }
            float s1 = r1[cl]/127.0f;
            g_a2[c] = s1*sw; g_bb2[c] = b2[c] - m2[c]*sc;
        }
    } else {
        int o = bid - (CMID + 9);
        float sc = g3[o] * rsqrtf(v3[o] + 1e-5f);
        float f0 = w3[o*CMID + t      ]*sc;
        float f1 = w3[o*CMID + t + 192]*sc;
        float f2 = w3[o*CMID + t + 384]*sc;
        float amx = fmaxf(fabsf(f0), fmaxf(fabsf(f1), fabsf(f2)));
        #pragma unroll
        for (int off=16; off; off>>=1) amx = fmaxf(amx, __shfl_xor_sync(0xffffffffu, amx, off));
        if ((t & 31) == 0) red[t>>5] = amx;
        __syncthreads();
        float mx = red[0];
        #pragma unroll
        for (int i=1;i<6;i++) mx = fmaxf(mx, red[i]);
        float sw = mx / 127.0f;
        int8_t* dst = (int8_t*)g_w3q + o*CMID;
        dst[t      ] = (int8_t)clampf(rintf(f0/sw), -127.f, 127.f);
        dst[t + 192] = (int8_t)clampf(rintf(f1/sw), -127.f, 127.f);
        dst[t + 384] = (int8_t)clampf(rintf(f2/sw), -127.f, 127.f);
        if (t == 0){
            float s2 = r2[cl]/127.0f;
            g_a3[o] = s2*sw; g_bb3[o] = b3[o] - m3[o]*sc;
        }
    }
}

// ---------------- stage 0: quantize x ----------------
__global__ __launch_bounds__(128) void k_qx(const float* __restrict__ x){
    __shared__ int8_t sq[CIN*128];
    int t  = threadIdx.x;
    int p0 = blockIdx.x*128;
    int p  = p0 + t;
    int b  = p / HWp, hw = p % HWp;
    const float* xb = x + (size_t)b*CIN*HWp + hw;
    float inv0 = 1.0f / g_s[0];
    #pragma unroll 4
    for (int c=0;c<CIN;c++){
        float q = clampf(rintf(xb[(size_t)c*HWp] * inv0), -127.f, 127.f);
        sq[c*128 + t] = (int8_t)q;
    }
    __syncthreads();
    uint32_t* ow = g_xq + (size_t)p0*KW1;
    for (int w=t; w<128*KW1; w+=128){
        int pl = w / KW1;
        int c0 = (w % KW1)*4;
        uint32_t v =  (uint32_t)(uint8_t)sq[(c0+0)*128+pl]
                   | ((uint32_t)(uint8_t)sq[(c0+1)*128+pl] << 8)
                   | ((uint32_t)(uint8_t)sq[(c0+2)*128+pl] << 16)
                   | ((uint32_t)(uint8_t)sq[(c0+3)*128+pl] << 24);
        ow[w] = v;
    }
}

// ---------------- fused conv1 + depthwise, quarter-image slabs, 3 CTA/SM ----------------
// block = (ch chunk 0..8, img, quarter 0..3). Slab = 9 rows (7 out + halo) x 28 = 252 px (pad to 256).
#define SAW  28            // A/W smem pitch (words) = 112 B
#define SPX  256           // padded slab px (252 data)
#define Y1S  65            // y1 per-channel stride (words); 63 data words
#define D_OFF_W  (SPX*SAW)                 // 7168
#define D_OFF_Y1 (D_OFF_W + 64*SAW)        // 8960
#define D_OFF_SC (D_OFF_Y1 + 64*Y1S)       // 13120
#define D_WORDS  (D_OFF_SC + 128)          // 13248
#define D_BYTES  (D_WORDS*4)               // 52992
__global__ __launch_bounds__(256,3) void k_c1dw(){
    extern __shared__ __align__(16) uint32_t sm[];
    uint32_t* y1 = sm + D_OFF_Y1;
    float* sAf = (float*)(sm + D_OFF_SC);
    float* sBf = (float*)(sm + D_OFF_SC + 64);
    int t    = threadIdx.x;
    int ch   = blockIdx.x;
    int img  = blockIdx.y;
    int qtr  = blockIdx.z;
    int off  = qtr*196 - 28;       // slab px -> image px offset
    uint32_t sbase = smem_u32(sm);

    if (t < 64){ sAf[t] = g_a1[ch*64+t]; sBf[t] = g_bb1[ch*64+t]; }
    const uint32_t* Aim = g_xq + (size_t)img*HWp*KW1;
    for (int i=t; i<SPX*6; i+=256){
        int sp = i/6, q = i%6;
        int ip = sp + off;
        uint32_t v = (sp < 252 && (unsigned)ip < (unsigned)HWp) ? 16u : 0u;
        cpa16z(sbase + (uint32_t)(sp*SAW + q*4)*4, &Aim[(v? ip:0)*KW1 + q*4], v);
    }
    for (int i=t; i<64*6; i+=256){
        int r = i/6, q = i%6;
        cpa16(sbase + (uint32_t)(D_OFF_W + r*SAW + q*4)*4, &g_w1q[(ch*64+r)*KW1 + q*4]);
    }
    cp_commit_wait();
    __syncthreads();

    int lane = t & 31, warp = t >> 5, r4 = lane >> 2, w4 = lane & 3;
    float inv1 = 1.0f / g_s[1];
    int8_t* y1b = (int8_t*)y1;
    uint32_t aLane = sbase + ((lane&7) + ((lane>>3)&1)*8)*112 + ((lane>>4)&1)*16;
    uint32_t bLane = sbase + (uint32_t)D_OFF_W*4
                   + ((lane&7) + ((lane>>4)&1)*8)*112 + ((lane>>3)&1)*16;

    #pragma unroll
    for (int tile = warp; tile < 16; tile += 8){
        int m0 = tile*16;
        int acc[8][4] = {};
        #pragma unroll
        for (int kc=0;kc<3;kc++){
            uint32_t a0,a1,a2,a3;
            ldm_x4(a0,a1,a2,a3, aLane + (uint32_t)(m0*112 + kc*32));
            #pragma unroll
            for (int tp=0; tp<4; tp++){
                uint32_t b0,b1,b2,b3;
                ldm_x4(b0,b1,b2,b3, bLane + (uint32_t)(tp*16*112 + kc*32));
                imma(acc[2*tp  ][0],acc[2*tp  ][1],acc[2*tp  ][2],acc[2*tp  ][3],
                     a0,a1,a2,a3, b0,b1);
                imma(acc[2*tp+1][0],acc[2*tp+1][1],acc[2*tp+1][2],acc[2*tp+1][3],
                     a0,a1,a2,a3, b2,b3);
            }
        }
        int px0 = m0 + r4, px1 = px0 + 8;
        bool s0ok = px0 < 252, s1ok = px1 < 252;
        bool v0 = s0ok && (unsigned)(px0 + off) < (unsigned)HWp;
        bool v1 = s1ok && (unsigned)(px1 + off) < (unsigned)HWp;
        #pragma unroll
        for (int ni=0;ni<8;ni++){
            int c0 = ni*8 + 2*w4;
            float af0 = sAf[c0], af1 = sAf[c0+1];
            float bb0 = sBf[c0], bb1 = sBf[c0+1];
            float q0 = fminf(rintf(clampf(fmaf(af0,(float)acc[ni][0],bb0),0.f,6.f)*inv1),127.f);
            float q1 = fminf(rintf(clampf(fmaf(af1,(float)acc[ni][1],bb1),0.f,6.f)*inv1),127.f);
            float q2 = fminf(rintf(clampf(fmaf(af0,(float)acc[ni][2],bb0),0.f,6.f)*inv1),127.f);
            float q3 = fminf(rintf(clampf(fmaf(af1,(float)acc[ni][3],bb1),0.f,6.f)*inv1),127.f);
            if (s0ok){
                y1b[ c0   *260 + px0] = v0 ? (int8_t)(int)q0 : (int8_t)0;
                y1b[(c0+1)*260 + px0] = v0 ? (int8_t)(int)q1 : (int8_t)0;
            }
            if (s1ok){
                y1b[ c0   *260 + px1] = v1 ? (int8_t)(int)q2 : (int8_t)0;
                y1b[(c0+1)*260 + px1] = v1 ? (int8_t)(int)q3 : (int8_t)0;
            }
        }
    }
    __syncthreads();

    // depthwise: output rows j=0..6 use y1 slab rows j, j+1, j+2
    float inv2 = 1.0f / g_s[2];
    int8_t* y2b = (int8_t*)sm;     // alias over A region (free after MMA)
    for (int task=t; task<64*7; task+=256){
        int c = task & 63, j = task >> 6;
        int cg = ch*64 + c;
        uint32_t wk0 = g_w2q[cg*3+0], wk1 = g_w2q[cg*3+1], wk2 = g_w2q[cg*3+2];
        float a2 = g_a2[cg], b2 = g_bb2[cg];
        const uint32_t* rw = y1 + c*Y1S;
        uint32_t rm[7], rc[7], rp[7];
        #pragma unroll
        for (int q=0;q<7;q++){
            rm[q] = rw[ j   *7 + q];
            rc[q] = rw[(j+1)*7 + q];
            rp[q] = rw[(j+2)*7 + q];
        }
        uint32_t pm=0, pc=0, pp=0;
        #pragma unroll
        for (int w=0; w<7; w++){
            uint32_t nm = (w<6)? rm[w+1] : 0u;
            uint32_t nc = (w<6)? rc[w+1] : 0u;
            uint32_t np = (w<6)? rp[w+1] : 0u;
            int o0 = __dp4a((int)__byte_perm(pm, rm[w], 0x6543), (int)wk0, 0)
                   + __dp4a((int)__byte_perm(pc, rc[w], 0x6543), (int)wk1, 0)
                   + __dp4a((int)__byte_perm(pp, rp[w], 0x6543), (int)wk2, 0);
            int o1 = __dp4a((int)rm[w], (int)wk0, 0)
                   + __dp4a((int)rc[w], (int)wk1, 0)
                   + __dp4a((int)rp[w], (int)wk2, 0);
            int o2 = __dp4a((int)__byte_perm(rm[w], nm, 0x4321), (int)wk0, 0)
                   + __dp4a((int)__byte_perm(rc[w], nc, 0x4321), (int)wk1, 0)
                   + __dp4a((int)__byte_perm(rp[w], np, 0x4321), (int)wk2, 0);
            int o3 = __dp4a((int)__byte_perm(rm[w], nm, 0x5432), (int)wk0, 0)
                   + __dp4a((int)__byte_perm(rc[w], nc, 0x5432), (int)wk1, 0)
                   + __dp4a((int)__byte_perm(rp[w], np, 0x5432), (int)wk2, 0);
            int outs[4] = {o0, o1, o2, o3};
            #pragma unroll
            for (int i2=0;i2<4;i2++){
                float y = clampf(fmaf(a2, (float)outs[i2], b2), 0.f, 6.f);
                int q = (int)fminf(rintf(y*inv2), 127.f);
                y2b[(j*28 + w*4 + i2)*64 + c] = (int8_t)q;
            }
            pm = rm[w]; pc = rc[w]; pp = rp[w];
        }
    }
    __syncthreads();

    uint32_t* dst = g_y2q + ((size_t)img*HWp + qtr*196)*KW3 + ch*16;
    const uint32_t* y2w = sm;
    for (int i=t; i<196*4; i+=256){
        int p = i>>2, q = i&3;
        *(uint4*)&dst[(size_t)p*KW3 + q*4] = *(const uint4*)&y2w[p*16 + q*4];
    }
}

// ---------------- conv3: 64px x 48ch, 256 thr, 3 CTA/SM ----------------
#define SB3 148
#define C3B  192                      // after 192 words of scale cache
#define C3A  (C3B + 48*SB3)           // 192 + 7104 = 7296
#define C3_WORDS (C3A + 64*SB3)       // + 9472 = 16768
#define C3_BYTES (C3_WORDS*4)         // 67072
__global__ __launch_bounds__(256,3) void k_conv3(const float* __restrict__ x,
                                                 float* __restrict__ out, int out_size){
    extern __shared__ __align__(16) uint32_t sm[];
    float* sa3 = (float*)sm;          // 96
    float* sb3 = (float*)(sm + 96);   // 96
    int t = threadIdx.x;
    int p0  = blockIdx.x*64;
    int cb0 = blockIdx.y*48;
    uint32_t sbase = smem_u32(sm);

    if (t < 96){ sa3[t] = g_a3[t]; sb3[t] = g_bb3[t]; }
    for (int i=t; i<48*36; i+=256){
        int r = i/36, q = i%36;
        cpa16(sbase + (uint32_t)(C3B + r*SB3 + q*4)*4, &g_w3q[(cb0+r)*KW3 + q*4]);
    }
    const uint32_t* Ag = g_y2q + (size_t)p0*KW3;
    for (int i=t; i<64*36; i+=256){
        int r = i/36, q = i%36;
        cpa16(sbase + (uint32_t)(C3A + r*SB3 + q*4)*4, &Ag[r*KW3 + q*4]);
    }
    cp_commit_wait();
    __syncthreads();

    int lane = t & 31, warp = t >> 5, r4 = lane >> 2, w4 = lane & 3;
    int m0 = (warp & 3)*16, n0 = (warp >> 2)*24;
    uint32_t aBase = sbase + (uint32_t)C3A*4
                   + (uint32_t)(m0 + (lane&7) + ((lane>>3)&1)*8)*592 + ((lane>>4)&1)*16;
    uint32_t bBase4 = sbase + (uint32_t)C3B*4
                   + (uint32_t)(n0 + (lane&7) + ((lane>>4)&1)*8)*592 + ((lane>>3)&1)*16;
    uint32_t bBase2 = sbase + (uint32_t)C3B*4
                   + (uint32_t)(n0 + 16 + (lane&7))*592 + ((lane>>3)&1)*16;
    int acc[3][4] = {};
    #pragma unroll 3
    for (int ks=0; ks<18; ks++){
        uint32_t a0,a1,a2,a3, b0,b1,b2,b3, b4,b5;
        ldm_x4(a0,a1,a2,a3, aBase + (uint32_t)ks*32);
        ldm_x4(b0,b1,b2,b3, bBase4 + (uint32_t)ks*32);
        imma(acc[0][0],acc[0][1],acc[0][2],acc[0][3], a0,a1,a2,a3, b0,b1);
        imma(acc[1][0],acc[1][1],acc[1][2],acc[1][3], a0,a1,a2,a3, b2,b3);
        ldm_x2(b4,b5, bBase2 + (uint32_t)ks*32);
        imma(acc[2][0],acc[2][1],acc[2][2],acc[2][3], a0,a1,a2,a3, b4,b5);
    }
    __syncthreads();
    float* sO = (float*)(sm + C3A);   // 64 x 49 floats, over A region
    #pragma unroll
    for (int ni=0; ni<3; ni++){
        int cl = n0 + ni*8 + 2*w4;
        float af0 = sa3[cb0+cl],  af1 = sa3[cb0+cl+1];
        float bf0 = sb3[cb0+cl],  bf1 = sb3[cb0+cl+1];
        int row0 = m0 + r4;
        sO[ row0   *49 + cl    ] = fmaf(af0, (float)acc[ni][0], bf0);
        sO[ row0   *49 + cl + 1] = fmaf(af1, (float)acc[ni][1], bf1);
        sO[(row0+8)*49 + cl    ] = fmaf(af0, (float)acc[ni][2], bf0);
        sO[(row0+8)*49 + cl + 1] = fmaf(af1, (float)acc[ni][3], bf1);
    }
    __syncthreads();
    float s3 = g_s[3];
    float inv3 = 1.0f / s3;
    for (int idx=t; idx<48*64; idx+=256){
        int cl = idx >> 6, pl = idx & 63;
        int c = cb0 + cl;
        int p = p0 + pl;
        int b = p / HWp, hw = p % HWp;
        size_t g = (size_t)b*CIN*HWp + (size_t)c*HWp + hw;
        float y = sO[pl*49 + cl] + x[g];
        float q = clampf(rintf(y*inv3), -127.f, 127.f);
        out[g] = q * s3;
    }
    if (blockIdx.x == 0 && blockIdx.y == 0){
        for (int i = OUT_ELEMS + t; i < out_size; i += 256) out[i] = g_s[3];
    }
}

// ---------------- launch ----------------
extern "C" void kernel_launch(void* const* d_in, const int* in_sizes, int n_in,
                              void* d_out, int out_size){
    const float* x  = (const float*)d_in[0];
    const float* w1 = (const float*)d_in[1];
    const float* g1 = (const float*)d_in[2];
    const float* b1 = (const float*)d_in[3];
    const float* m1 = (const float*)d_in[4];
    const float* v1 = (const float*)d_in[5];
    const float* w2 = (const float*)d_in[6];
    const float* g2 = (const float*)d_in[7];
    const float* b2 = (const float*)d_in[8];
    const float* m2 = (const float*)d_in[9];
    const float* v2 = (const float*)d_in[10];
    const float* w3 = (const float*)d_in[11];
    const float* g3 = (const float*)d_in[12];
    const float* b3 = (const float*)d_in[13];
    const float* m3 = (const float*)d_in[14];
    const float* v3 = (const float*)d_in[15];
    const float* r0 = (const float*)d_in[16];
    const float* r1 = (const float*)d_in[17];
    const float* r2 = (const float*)d_in[18];
    const float* r3 = (const float*)d_in[19];
    const int*   cl = (const int*)d_in[20];

    cudaFuncSetAttribute(k_c1dw,  cudaFuncAttributeMaxDynamicSharedMemorySize, D_BYTES);
    cudaFuncSetAttribute(k_conv3, cudaFuncAttributeMaxDynamicSharedMemorySize, C3_BYTES);

    k_prep<<<CMID + 9 + CIN, 192>>>(w1,g1,b1,m1,v1, w2,g2,b2,m2,v2, w3,g3,b3,m3,v3,
                                    r0,r1,r2,r3, cl);
    k_qx<<<NPIX/128, 128>>>(x);
    k_c1dw<<<dim3(9, NB, 4), 256, D_BYTES>>>();
    k_conv3<<<dim3(NPIX/64, 2), 256, C3_BYTES>>>(x, (float*)d_out, out_size);
}